// round 2
// baseline (speedup 1.0000x reference)
#include <cuda_runtime.h>

#define BSZ_   2
#define DM_    1024
#define QL_    2048
#define NH_    16
#define DH_    64
#define LOCAL_ 1000
#define SCALE_ 0.125f

// ---------------- scratch (__device__ globals; no allocation allowed) ----------
__device__ __align__(16) float g_Q[BSZ_*DM_*QL_];    // [b][n*64+d][pos]
__device__ __align__(16) float g_K[BSZ_*DM_*QL_];
__device__ __align__(16) float g_V[BSZ_*DM_*QL_];
__device__ __align__(16) float g_R[DM_*QL_];         // [n*64+d][pos]
__device__ __align__(16) float g_AV[BSZ_*DM_*QL_];   // attn_vec [b][n*64+d][pos]
__device__ __align__(16) float g_TMP[BSZ_*DM_*QL_];  // attn_out + residual

// ---------------- fp32 tiled GEMM: C[64x64] per block, K-tile 16 ---------------
// mode 0: W_qkv @ z1ss + u1ss  -> scatter to g_Q/g_K/g_V   (grid 32x48x2)
// mode 1: W_r   @ pos_emb      -> g_R                       (grid 32x16x1)
// mode 2: W_o   @ g_AV + b_o + z1ss -> g_TMP                (grid 32x16x2)
__global__ void __launch_bounds__(256) gemm_fused(
    const float* __restrict__ A, const float* __restrict__ Bbase,
    const float* __restrict__ U, const float* __restrict__ bias,
    int K, int mode)
{
    const int N = QL_;
    const int b = blockIdx.z;
    const float* B;
    if (mode == 2)      B = g_AV + (size_t)b * K * N;
    else if (mode == 0) B = Bbase + (size_t)b * K * N;
    else                B = Bbase;

    const int m0 = blockIdx.y * 64, n0 = blockIdx.x * 64;
    __shared__ float As[16][64];
    __shared__ float Bs[16][64];

    const int tid = threadIdx.x;
    const int tx = tid & 15, ty = tid >> 4;
    float acc[4][4] = {};

    for (int k0 = 0; k0 < K; k0 += 16) {
        {   // A tile: 64 rows x 16 k, store transposed
            int row = tid >> 2;
            int kk  = (tid & 3) * 4;
            float4 av = *(const float4*)&A[(size_t)(m0 + row) * K + k0 + kk];
            As[kk + 0][row] = av.x; As[kk + 1][row] = av.y;
            As[kk + 2][row] = av.z; As[kk + 3][row] = av.w;
        }
        {   // B tile: 16 k x 64 n
            int row = tid >> 4;
            int nn  = (tid & 15) * 4;
            *(float4*)&Bs[row][nn] = *(const float4*)&B[(size_t)(k0 + row) * N + n0 + nn];
        }
        __syncthreads();
        #pragma unroll
        for (int k = 0; k < 16; k++) {
            float4 a  = *(const float4*)&As[k][ty * 4];
            float4 bv = *(const float4*)&Bs[k][tx * 4];
            float ar[4] = {a.x, a.y, a.z, a.w};
            float br[4] = {bv.x, bv.y, bv.z, bv.w};
            #pragma unroll
            for (int i = 0; i < 4; i++)
                #pragma unroll
                for (int j = 0; j < 4; j++)
                    acc[i][j] += ar[i] * br[j];
        }
        __syncthreads();
    }

    #pragma unroll
    for (int i = 0; i < 4; i++) {
        int m = m0 + ty * 4 + i;
        #pragma unroll
        for (int j = 0; j < 4; j++) {
            int n = n0 + tx * 4 + j;
            float v = acc[i][j];
            if (mode == 0) {
                v += U[((size_t)b * 3 * DM_ + m) * QL_ + n];
                int which = m >> 10, rem = m & 1023;
                float* dst = (which == 0) ? g_Q : (which == 1) ? g_K : g_V;
                dst[((size_t)b * DM_ + rem) * QL_ + n] = v;
            } else if (mode == 1) {
                g_R[(size_t)m * QL_ + n] = v;
            } else {
                v += bias[m] + U[((size_t)b * DM_ + m) * QL_ + n];
                g_TMP[((size_t)b * DM_ + m) * QL_ + n] = v;
            }
        }
    }
}

// ---------------- banded flash attention with rel-shift -----------------------
// block = (qblock 64, head, batch); 256 threads; dynamic smem ~102 KB
#define SQ_S 68
#define SR_S 132
#define ATTN_SMEM ((4*64*SQ_S + 64*SR_S + 5*64) * sizeof(float))

__global__ void __launch_bounds__(256) attn_kernel(
    const float* __restrict__ rwb_all, const float* __restrict__ rrb_all)
{
    extern __shared__ float sm[];
    float* sQ  = sm;                    // [64][68]  (d, i)
    float* sK  = sQ + 64 * SQ_S;        // [64][68]  (d, j)
    float* sV  = sK + 64 * SQ_S;        // [64][68]  (d, j)
    float* sP  = sV + 64 * SQ_S;        // [64][68]  (i, j)
    float* sR  = sP + 64 * SQ_S;        // [64][132] (d, Lrel)
    float* sM  = sR + 64 * SR_S;
    float* sL  = sM + 64;
    float* sC  = sL + 64;
    float* srw = sC + 64;
    float* srr = srw + 64;

    const int b = blockIdx.z, n = blockIdx.y;
    const int i0 = blockIdx.x * 64;
    const int tid = threadIdx.x, tx = tid & 15, ty = tid >> 4;

    const float* Qg = g_Q + ((size_t)b * DM_ + n * DH_) * QL_;
    const float* Kg = g_K + ((size_t)b * DM_ + n * DH_) * QL_;
    const float* Vg = g_V + ((size_t)b * DM_ + n * DH_) * QL_;
    const float* Rg = g_R + (size_t)(n * DH_) * QL_;

    if (tid < 64) {
        srw[tid] = rwb_all[n * DH_ + tid];
        srr[tid] = rrb_all[n * DH_ + tid];
        sM[tid] = -1e30f;
        sL[tid] = 0.0f;
    }
    for (int idx = tid; idx < 64 * 64; idx += 256) {
        int d = idx >> 6, i = idx & 63;
        sQ[d * SQ_S + i] = Qg[(size_t)d * QL_ + i0 + i];
    }

    float acc[4][4] = {};
    int jlo = i0 - (LOCAL_ - 1); if (jlo < 0) jlo = 0; jlo &= ~63;

    for (int j0 = jlo; j0 <= i0 + 63; j0 += 64) {
        __syncthreads();
        for (int idx = tid; idx < 64 * 64; idx += 256) {
            int d = idx >> 6, j = idx & 63;
            sK[d * SQ_S + j] = Kg[(size_t)d * QL_ + j0 + j];
            sV[d * SQ_S + j] = Vg[(size_t)d * QL_ + j0 + j];
        }
        int rbase = j0 - i0 + (QL_ - 1) - 63;   // jrel for L=0
        for (int idx = tid; idx < 64 * 128; idx += 256) {
            int d = idx >> 7, L = idx & 127;
            int jr = rbase + L;
            sR[d * SR_S + L] = (jr >= 0 && jr < QL_) ? Rg[(size_t)d * QL_ + jr] : 0.0f;
        }
        __syncthreads();

        // ---- scores: S[i][j] over 4x4 micro-tile ----
        float s[4][4] = {};
        #pragma unroll 4
        for (int d = 0; d < 64; d++) {
            float w = srw[d], r = srr[d];
            float4 qf = *(const float4*)&sQ[d * SQ_S + ty * 4];
            float4 kf = *(const float4*)&sK[d * SQ_S + tx * 4];
            float qw[4] = {qf.x + w, qf.y + w, qf.z + w, qf.w + w};
            float qr[4] = {qf.x + r, qf.y + r, qf.z + r, qf.w + r};
            float kv[4] = {kf.x, kf.y, kf.z, kf.w};
            const float* rrow = &sR[d * SR_S + (tx * 4 - ty * 4 + 60)]; // L = 63 + (j-i), min offset
            float rv[7];
            #pragma unroll
            for (int u = 0; u < 7; u++) rv[u] = rrow[u];
            #pragma unroll
            for (int m = 0; m < 4; m++)
                #pragma unroll
                for (int t = 0; t < 4; t++)
                    s[m][t] += qw[m] * kv[t] + qr[m] * rv[t - m + 3];
        }

        // ---- mask + scale ----
        #pragma unroll
        for (int m = 0; m < 4; m++)
            #pragma unroll
            for (int t = 0; t < 4; t++) {
                int gi = i0 + ty * 4 + m, gj = j0 + tx * 4 + t;
                bool ok = (gj <= gi) && (gj > gi - LOCAL_);
                s[m][t] = ok ? s[m][t] * SCALE_ : -1e30f;
            }

        // ---- online softmax (row = i group = fixed ty -> 16 tx lanes in warp) --
        float rmax[4], rsum[4], mo[4], mn[4];
        #pragma unroll
        for (int m = 0; m < 4; m++) {
            rmax[m] = fmaxf(fmaxf(s[m][0], s[m][1]), fmaxf(s[m][2], s[m][3]));
        }
        #pragma unroll
        for (int o = 8; o >= 1; o >>= 1)
            #pragma unroll
            for (int m = 0; m < 4; m++)
                rmax[m] = fmaxf(rmax[m], __shfl_xor_sync(0xffffffffu, rmax[m], o));
        #pragma unroll
        for (int m = 0; m < 4; m++) {
            mo[m] = sM[ty * 4 + m];
            mn[m] = fmaxf(mo[m], rmax[m]);
            rsum[m] = 0.0f;
            #pragma unroll
            for (int t = 0; t < 4; t++) {
                float p = __expf(s[m][t] - mn[m]);
                s[m][t] = p;
                rsum[m] += p;
            }
        }
        #pragma unroll
        for (int o = 8; o >= 1; o >>= 1)
            #pragma unroll
            for (int m = 0; m < 4; m++)
                rsum[m] += __shfl_xor_sync(0xffffffffu, rsum[m], o);
        __syncwarp();
        if (tx == 0) {
            #pragma unroll
            for (int m = 0; m < 4; m++) {
                int i = ty * 4 + m;
                float cc = __expf(mo[m] - mn[m]);
                sC[i] = cc;
                sL[i] = sL[i] * cc + rsum[m];
                sM[i] = mn[m];
            }
        }
        #pragma unroll
        for (int m = 0; m < 4; m++)
            #pragma unroll
            for (int t = 0; t < 4; t++)
                sP[(ty * 4 + m) * SQ_S + tx * 4 + t] = s[m][t];
        __syncthreads();

        // ---- O[d][i] update: acc micro-tile = (d: ty*4+m, i: tx*4+t) ----
        float cf[4];
        #pragma unroll
        for (int t = 0; t < 4; t++) cf[t] = sC[tx * 4 + t];
        #pragma unroll
        for (int m = 0; m < 4; m++)
            #pragma unroll
            for (int t = 0; t < 4; t++)
                acc[m][t] *= cf[t];
        #pragma unroll 4
        for (int j = 0; j < 64; j++) {
            float vv[4], pp[4];
            #pragma unroll
            for (int m = 0; m < 4; m++) vv[m] = sV[(ty * 4 + m) * SQ_S + j];
            #pragma unroll
            for (int t = 0; t < 4; t++) pp[t] = sP[(tx * 4 + t) * SQ_S + j];
            #pragma unroll
            for (int m = 0; m < 4; m++)
                #pragma unroll
                for (int t = 0; t < 4; t++)
                    acc[m][t] += vv[m] * pp[t];
        }
    }

    float* AVg = g_AV + ((size_t)b * DM_ + n * DH_) * QL_;
    #pragma unroll
    for (int m = 0; m < 4; m++) {
        int d = ty * 4 + m;
        #pragma unroll
        for (int t = 0; t < 4; t++) {
            int i = tx * 4 + t;
            AVg[(size_t)d * QL_ + i0 + i] = acc[m][t] / sL[i];
        }
    }
}

// ---------------- post-LN over d_model per (b, q) ------------------------------
__global__ void __launch_bounds__(256) ln_kernel(float* __restrict__ out)
{
    const int b  = blockIdx.y;
    const int tx = threadIdx.x & 31;
    const int ty = threadIdx.x >> 5;            // 0..7
    const int q  = blockIdx.x * 32 + tx;
    const float* X = g_TMP + (size_t)b * DM_ * QL_;

    float s = 0.0f, s2 = 0.0f;
    for (int o = ty; o < DM_; o += 8) {
        float v = X[(size_t)o * QL_ + q];
        s += v; s2 += v * v;
    }
    __shared__ float sh[8][32], sh2[8][32];
    __shared__ float mu[32], rs[32];
    sh[ty][tx] = s; sh2[ty][tx] = s2;
    __syncthreads();
    if (ty == 0) {
        float ts = 0.0f, ts2 = 0.0f;
        #pragma unroll
        for (int k = 0; k < 8; k++) { ts += sh[k][tx]; ts2 += sh2[k][tx]; }
        float m = ts * (1.0f / DM_);
        float var = ts2 * (1.0f / DM_) - m * m;
        mu[tx] = m;
        rs[tx] = rsqrtf(var + 1e-5f);
    }
    __syncthreads();
    float m = mu[tx], r = rs[tx];
    float* O = out + (size_t)b * DM_ * QL_;
    for (int o = ty; o < DM_; o += 8)
        O[(size_t)o * QL_ + q] = (X[(size_t)o * QL_ + q] - m) * r;
}

// ---------------- launch --------------------------------------------------------
extern "C" void kernel_launch(void* const* d_in, const int* in_sizes, int n_in,
                              void* d_out, int out_size)
{
    const float* z1ss = (const float*)d_in[0];
    const float* pos  = (const float*)d_in[1];
    const float* u1ss = (const float*)d_in[2];
    const float* Wqkv = (const float*)d_in[3];
    const float* Wr   = (const float*)d_in[4];
    const float* rwb  = (const float*)d_in[5];
    const float* rrb  = (const float*)d_in[6];
    const float* Wo   = (const float*)d_in[7];
    const float* bo   = (const float*)d_in[8];
    float* out = (float*)d_out;

    cudaFuncSetAttribute(attn_kernel,
                         cudaFuncAttributeMaxDynamicSharedMemorySize,
                         (int)ATTN_SMEM);

    dim3 g0(QL_ / 64, (3 * DM_) / 64, BSZ_);
    gemm_fused<<<g0, 256>>>(Wqkv, z1ss, u1ss, nullptr, DM_, 0);

    dim3 g1(QL_ / 64, DM_ / 64, 1);
    gemm_fused<<<g1, 256>>>(Wr, pos, nullptr, nullptr, DM_, 1);

    dim3 ga(QL_ / 64, NH_, BSZ_);
    attn_kernel<<<ga, 256, ATTN_SMEM>>>(rwb, rrb);

    dim3 g2(QL_ / 64, DM_ / 64, BSZ_);
    gemm_fused<<<g2, 256>>>(Wo, nullptr, z1ss, bo, DM_, 2);

    dim3 g3(QL_ / 32, BSZ_);
    ln_kernel<<<g3, 256>>>(out);
}

// round 3
// speedup vs baseline: 1.3621x; 1.3621x over previous
#include <cuda_runtime.h>
#include <cstdint>

#define BSZ_   2
#define DM_    1024
#define QL_    2048
#define NH_    16
#define DH_    64
#define LOCAL_ 1000
#define SCALE_ 0.125f

// ---------------- scratch (__device__ globals; no allocation allowed) ----------
__device__ __align__(16) float g_Q[BSZ_*DM_*QL_];    // [b][n*64+d][pos]
__device__ __align__(16) float g_K[BSZ_*DM_*QL_];
__device__ __align__(16) float g_V[BSZ_*DM_*QL_];
__device__ __align__(16) float g_R[DM_*QL_];         // [n*64+d][pos]
__device__ __align__(16) float g_AV[BSZ_*DM_*QL_];   // attn_vec [b][n*64+d][pos]
__device__ __align__(16) float g_TMP[BSZ_*DM_*QL_];  // attn_out + residual

// =====================================================================
// tf32 tensor-core GEMM: C[128x128] per CTA, warp tile 64x32, K-tile 32
// mode 0: W_qkv @ z1ss + u1ss  -> scatter g_Q/g_K/g_V
// mode 1: W_r   @ pos_emb      -> g_R
// mode 2: W_o   @ g_AV + b_o + z1ss -> g_TMP
// =====================================================================
__device__ __forceinline__ uint32_t f2tf32(float f) {
    uint32_t o; asm("cvt.rna.tf32.f32 %0, %1;" : "=r"(o) : "f"(f)); return o;
}

#define GK_STRIDE 136
#define GK_BUF    (32 * GK_STRIDE)
#define GEMM_SMEM (4 * GK_BUF * 4)   // 2 bufs A + 2 bufs B, 4B words

#define MMA_TF32(C, Af, Bf)                                                     \
    asm volatile(                                                               \
        "mma.sync.aligned.m16n8k8.row.col.f32.tf32.tf32.f32 "                   \
        "{%0,%1,%2,%3}, {%4,%5,%6,%7}, {%8,%9}, {%0,%1,%2,%3};"                 \
        : "+f"((C)[0]), "+f"((C)[1]), "+f"((C)[2]), "+f"((C)[3])                \
        : "r"((Af)[0]), "r"((Af)[1]), "r"((Af)[2]), "r"((Af)[3]),               \
          "r"((Bf)[0]), "r"((Bf)[1]))

__global__ void __launch_bounds__(256, 1) gemm_tc(
    const float* __restrict__ A, const float* __restrict__ Bbase,
    const float* __restrict__ U, const float* __restrict__ bias,
    int K, int mode)
{
    extern __shared__ uint32_t smem_u[];
    uint32_t* Abuf = smem_u;                 // [2][32][136]
    uint32_t* Bbuf = smem_u + 2 * GK_BUF;    // [2][32][136]

    const int N = QL_;
    const int b = blockIdx.z;
    const float* B = (mode == 2) ? g_AV + (size_t)b * K * N
                   : (mode == 0) ? Bbase + (size_t)b * K * N
                   : Bbase;

    const int m0 = blockIdx.y * 128, n0 = blockIdx.x * 128;
    const int tid  = threadIdx.x;
    const int wid  = tid >> 5, lane = tid & 31;
    const int g    = lane >> 2, q = lane & 3;
    const int wm   = wid >> 2, wn = wid & 3;

    // gmem load mapping
    const int am = tid >> 1, akq = (tid & 1) * 16;     // A: 128 rows x 32 k
    const int bk = tid >> 3, bn = (tid & 7) * 16;      // B: 32 k x 128 n

    const float* Ag = A + (size_t)(m0 + am) * K + akq;
    const float* Bg = B + (size_t)bk * N + n0 + bn;

    float4 ra[4], rb[4];

    float acc[4][4][4];
    #pragma unroll
    for (int i = 0; i < 4; i++)
        #pragma unroll
        for (int j = 0; j < 4; j++)
            #pragma unroll
            for (int c = 0; c < 4; c++) acc[i][j][c] = 0.0f;

    // prologue load of tile 0
    #pragma unroll
    for (int i = 0; i < 4; i++) ra[i] = *(const float4*)(Ag + 4 * i);
    #pragma unroll
    for (int i = 0; i < 4; i++) rb[i] = *(const float4*)(Bg + 4 * i);
    {
        uint32_t* As = Abuf; uint32_t* Bs = Bbuf;
        #pragma unroll
        for (int i = 0; i < 4; i++) {
            float v[4] = {ra[i].x, ra[i].y, ra[i].z, ra[i].w};
            #pragma unroll
            for (int c = 0; c < 4; c++)
                As[(akq + 4 * i + c) * GK_STRIDE + am] = f2tf32(v[c]);
        }
        #pragma unroll
        for (int i = 0; i < 4; i++) {
            uint4 o = {f2tf32(rb[i].x), f2tf32(rb[i].y), f2tf32(rb[i].z), f2tf32(rb[i].w)};
            *(uint4*)&Bs[bk * GK_STRIDE + bn + 4 * i] = o;
        }
    }

    int cur = 0;
    for (int k0 = 0; k0 < K; k0 += 32) {
        __syncthreads();
        const bool nxt = (k0 + 32 < K);
        if (nxt) {
            #pragma unroll
            for (int i = 0; i < 4; i++) ra[i] = *(const float4*)(Ag + k0 + 32 + 4 * i);
            #pragma unroll
            for (int i = 0; i < 4; i++) rb[i] = *(const float4*)(Bg + (size_t)(k0 + 32) * N + 4 * i);
        }

        const uint32_t* As = Abuf + cur * GK_BUF;
        const uint32_t* Bs = Bbuf + cur * GK_BUF;
        #pragma unroll
        for (int kk = 0; kk < 4; kk++) {
            const int kb = kk * 8;
            uint32_t af[4][4], bf[4][2];
            #pragma unroll
            for (int tm = 0; tm < 4; tm++) {
                const int m = wm * 64 + tm * 16 + g;
                af[tm][0] = As[(kb + q) * GK_STRIDE + m];
                af[tm][1] = As[(kb + q) * GK_STRIDE + m + 8];
                af[tm][2] = As[(kb + q + 4) * GK_STRIDE + m];
                af[tm][3] = As[(kb + q + 4) * GK_STRIDE + m + 8];
            }
            #pragma unroll
            for (int tn = 0; tn < 4; tn++) {
                const int n = wn * 32 + tn * 8 + g;
                bf[tn][0] = Bs[(kb + q) * GK_STRIDE + n];
                bf[tn][1] = Bs[(kb + q + 4) * GK_STRIDE + n];
            }
            #pragma unroll
            for (int tm = 0; tm < 4; tm++)
                #pragma unroll
                for (int tn = 0; tn < 4; tn++)
                    MMA_TF32(acc[tm][tn], af[tm], bf[tn]);
        }

        if (nxt) {
            uint32_t* Asw = Abuf + (cur ^ 1) * GK_BUF;
            uint32_t* Bsw = Bbuf + (cur ^ 1) * GK_BUF;
            #pragma unroll
            for (int i = 0; i < 4; i++) {
                float v[4] = {ra[i].x, ra[i].y, ra[i].z, ra[i].w};
                #pragma unroll
                for (int c = 0; c < 4; c++)
                    Asw[(akq + 4 * i + c) * GK_STRIDE + am] = f2tf32(v[c]);
            }
            #pragma unroll
            for (int i = 0; i < 4; i++) {
                uint4 o = {f2tf32(rb[i].x), f2tf32(rb[i].y), f2tf32(rb[i].z), f2tf32(rb[i].w)};
                *(uint4*)&Bsw[bk * GK_STRIDE + bn + 4 * i] = o;
            }
        }
        cur ^= 1;
    }

    // ---------------- epilogue ----------------
    #pragma unroll
    for (int tm = 0; tm < 4; tm++) {
        #pragma unroll
        for (int half = 0; half < 2; half++) {
            const int m = m0 + wm * 64 + tm * 16 + g + half * 8;
            #pragma unroll
            for (int tn = 0; tn < 4; tn++) {
                const int n = n0 + wn * 32 + tn * 8 + 2 * q;
                float v0 = acc[tm][tn][half * 2 + 0];
                float v1 = acc[tm][tn][half * 2 + 1];
                if (mode == 0) {
                    const float2 u = *(const float2*)&U[((size_t)b * 3 * DM_ + m) * QL_ + n];
                    v0 += u.x; v1 += u.y;
                    const int which = m >> 10, rem = m & 1023;
                    float* dst = (which == 0) ? g_Q : (which == 1) ? g_K : g_V;
                    *(float2*)&dst[((size_t)b * DM_ + rem) * QL_ + n] = make_float2(v0, v1);
                } else if (mode == 1) {
                    *(float2*)&g_R[(size_t)m * QL_ + n] = make_float2(v0, v1);
                } else {
                    const float bb = bias[m];
                    const float2 u = *(const float2*)&U[((size_t)b * DM_ + m) * QL_ + n];
                    v0 += bb + u.x; v1 += bb + u.y;
                    *(float2*)&g_TMP[((size_t)b * DM_ + m) * QL_ + n] = make_float2(v0, v1);
                }
            }
        }
    }
}

// ---------------- banded flash attention with rel-shift (unchanged) -----------
#define SQ_S 68
#define SR_S 132
#define ATTN_SMEM ((4*64*SQ_S + 64*SR_S + 5*64) * sizeof(float))

__global__ void __launch_bounds__(256) attn_kernel(
    const float* __restrict__ rwb_all, const float* __restrict__ rrb_all)
{
    extern __shared__ float sm[];
    float* sQ  = sm;                    // [64][68]  (d, i)
    float* sK  = sQ + 64 * SQ_S;        // [64][68]  (d, j)
    float* sV  = sK + 64 * SQ_S;        // [64][68]  (d, j)
    float* sP  = sV + 64 * SQ_S;        // [64][68]  (i, j)
    float* sR  = sP + 64 * SQ_S;        // [64][132] (d, Lrel)
    float* sM  = sR + 64 * SR_S;
    float* sL  = sM + 64;
    float* sC  = sL + 64;
    float* srw = sC + 64;
    float* srr = srw + 64;

    const int b = blockIdx.z, n = blockIdx.y;
    const int i0 = blockIdx.x * 64;
    const int tid = threadIdx.x, tx = tid & 15, ty = tid >> 4;

    const float* Qg = g_Q + ((size_t)b * DM_ + n * DH_) * QL_;
    const float* Kg = g_K + ((size_t)b * DM_ + n * DH_) * QL_;
    const float* Vg = g_V + ((size_t)b * DM_ + n * DH_) * QL_;
    const float* Rg = g_R + (size_t)(n * DH_) * QL_;

    if (tid < 64) {
        srw[tid] = rwb_all[n * DH_ + tid];
        srr[tid] = rrb_all[n * DH_ + tid];
        sM[tid] = -1e30f;
        sL[tid] = 0.0f;
    }
    for (int idx = tid; idx < 64 * 64; idx += 256) {
        int d = idx >> 6, i = idx & 63;
        sQ[d * SQ_S + i] = Qg[(size_t)d * QL_ + i0 + i];
    }

    float acc[4][4] = {};
    int jlo = i0 - (LOCAL_ - 1); if (jlo < 0) jlo = 0; jlo &= ~63;

    for (int j0 = jlo; j0 <= i0 + 63; j0 += 64) {
        __syncthreads();
        for (int idx = tid; idx < 64 * 64; idx += 256) {
            int d = idx >> 6, j = idx & 63;
            sK[d * SQ_S + j] = Kg[(size_t)d * QL_ + j0 + j];
            sV[d * SQ_S + j] = Vg[(size_t)d * QL_ + j0 + j];
        }
        int rbase = j0 - i0 + (QL_ - 1) - 63;   // jrel for L=0
        for (int idx = tid; idx < 64 * 128; idx += 256) {
            int d = idx >> 7, L = idx & 127;
            int jr = rbase + L;
            sR[d * SR_S + L] = (jr >= 0 && jr < QL_) ? Rg[(size_t)d * QL_ + jr] : 0.0f;
        }
        __syncthreads();

        float s[4][4] = {};
        #pragma unroll 4
        for (int d = 0; d < 64; d++) {
            float w = srw[d], r = srr[d];
            float4 qf = *(const float4*)&sQ[d * SQ_S + ty * 4];
            float4 kf = *(const float4*)&sK[d * SQ_S + tx * 4];
            float qw[4] = {qf.x + w, qf.y + w, qf.z + w, qf.w + w};
            float qr[4] = {qf.x + r, qf.y + r, qf.z + r, qf.w + r};
            float kv[4] = {kf.x, kf.y, kf.z, kf.w};
            const float* rrow = &sR[d * SR_S + (tx * 4 - ty * 4 + 60)];
            float rv[7];
            #pragma unroll
            for (int u = 0; u < 7; u++) rv[u] = rrow[u];
            #pragma unroll
            for (int m = 0; m < 4; m++)
                #pragma unroll
                for (int t = 0; t < 4; t++)
                    s[m][t] += qw[m] * kv[t] + qr[m] * rv[t - m + 3];
        }

        #pragma unroll
        for (int m = 0; m < 4; m++)
            #pragma unroll
            for (int t = 0; t < 4; t++) {
                int gi = i0 + ty * 4 + m, gj = j0 + tx * 4 + t;
                bool ok = (gj <= gi) && (gj > gi - LOCAL_);
                s[m][t] = ok ? s[m][t] * SCALE_ : -1e30f;
            }

        float rmax[4], rsum[4], mo[4], mn[4];
        #pragma unroll
        for (int m = 0; m < 4; m++)
            rmax[m] = fmaxf(fmaxf(s[m][0], s[m][1]), fmaxf(s[m][2], s[m][3]));
        #pragma unroll
        for (int o = 8; o >= 1; o >>= 1)
            #pragma unroll
            for (int m = 0; m < 4; m++)
                rmax[m] = fmaxf(rmax[m], __shfl_xor_sync(0xffffffffu, rmax[m], o));
        #pragma unroll
        for (int m = 0; m < 4; m++) {
            mo[m] = sM[ty * 4 + m];
            mn[m] = fmaxf(mo[m], rmax[m]);
            rsum[m] = 0.0f;
            #pragma unroll
            for (int t = 0; t < 4; t++) {
                float p = __expf(s[m][t] - mn[m]);
                s[m][t] = p;
                rsum[m] += p;
            }
        }
        #pragma unroll
        for (int o = 8; o >= 1; o >>= 1)
            #pragma unroll
            for (int m = 0; m < 4; m++)
                rsum[m] += __shfl_xor_sync(0xffffffffu, rsum[m], o);
        __syncwarp();
        if (tx == 0) {
            #pragma unroll
            for (int m = 0; m < 4; m++) {
                int i = ty * 4 + m;
                float cc = __expf(mo[m] - mn[m]);
                sC[i] = cc;
                sL[i] = sL[i] * cc + rsum[m];
                sM[i] = mn[m];
            }
        }
        #pragma unroll
        for (int m = 0; m < 4; m++)
            #pragma unroll
            for (int t = 0; t < 4; t++)
                sP[(ty * 4 + m) * SQ_S + tx * 4 + t] = s[m][t];
        __syncthreads();

        float cf[4];
        #pragma unroll
        for (int t = 0; t < 4; t++) cf[t] = sC[tx * 4 + t];
        #pragma unroll
        for (int m = 0; m < 4; m++)
            #pragma unroll
            for (int t = 0; t < 4; t++)
                acc[m][t] *= cf[t];
        #pragma unroll 4
        for (int j = 0; j < 64; j++) {
            float vv[4], pp[4];
            #pragma unroll
            for (int m = 0; m < 4; m++) vv[m] = sV[(ty * 4 + m) * SQ_S + j];
            #pragma unroll
            for (int t = 0; t < 4; t++) pp[t] = sP[(tx * 4 + t) * SQ_S + j];
            #pragma unroll
            for (int m = 0; m < 4; m++)
                #pragma unroll
                for (int t = 0; t < 4; t++)
                    acc[m][t] += vv[m] * pp[t];
        }
    }

    float* AVg = g_AV + ((size_t)b * DM_ + n * DH_) * QL_;
    #pragma unroll
    for (int m = 0; m < 4; m++) {
        int d = ty * 4 + m;
        #pragma unroll
        for (int t = 0; t < 4; t++) {
            int i = tx * 4 + t;
            AVg[(size_t)d * QL_ + i0 + i] = acc[m][t] / sL[i];
        }
    }
}

// ---------------- post-LN over d_model per (b, q) ------------------------------
__global__ void __launch_bounds__(256) ln_kernel(float* __restrict__ out)
{
    const int b  = blockIdx.y;
    const int tx = threadIdx.x & 31;
    const int ty = threadIdx.x >> 5;
    const int q  = blockIdx.x * 32 + tx;
    const float* X = g_TMP + (size_t)b * DM_ * QL_;

    float s = 0.0f, s2 = 0.0f;
    for (int o = ty; o < DM_; o += 8) {
        float v = X[(size_t)o * QL_ + q];
        s += v; s2 += v * v;
    }
    __shared__ float sh[8][32], sh2[8][32];
    __shared__ float mu[32], rs[32];
    sh[ty][tx] = s; sh2[ty][tx] = s2;
    __syncthreads();
    if (ty == 0) {
        float ts = 0.0f, ts2 = 0.0f;
        #pragma unroll
        for (int k = 0; k < 8; k++) { ts += sh[k][tx]; ts2 += sh2[k][tx]; }
        float m = ts * (1.0f / DM_);
        float var = ts2 * (1.0f / DM_) - m * m;
        mu[tx] = m;
        rs[tx] = rsqrtf(var + 1e-5f);
    }
    __syncthreads();
    float m = mu[tx], r = rs[tx];
    float* O = out + (size_t)b * DM_ * QL_;
    for (int o = ty; o < DM_; o += 8)
        O[(size_t)o * QL_ + q] = (X[(size_t)o * QL_ + q] - m) * r;
}

// ---------------- launch --------------------------------------------------------
extern "C" void kernel_launch(void* const* d_in, const int* in_sizes, int n_in,
                              void* d_out, int out_size)
{
    const float* z1ss = (const float*)d_in[0];
    const float* pos  = (const float*)d_in[1];
    const float* u1ss = (const float*)d_in[2];
    const float* Wqkv = (const float*)d_in[3];
    const float* Wr   = (const float*)d_in[4];
    const float* rwb  = (const float*)d_in[5];
    const float* rrb  = (const float*)d_in[6];
    const float* Wo   = (const float*)d_in[7];
    const float* bo   = (const float*)d_in[8];
    float* out = (float*)d_out;

    cudaFuncSetAttribute(attn_kernel,
                         cudaFuncAttributeMaxDynamicSharedMemorySize,
                         (int)ATTN_SMEM);
    cudaFuncSetAttribute(gemm_tc,
                         cudaFuncAttributeMaxDynamicSharedMemorySize,
                         GEMM_SMEM);

    dim3 g0(QL_ / 128, (3 * DM_) / 128, BSZ_);
    gemm_tc<<<g0, 256, GEMM_SMEM>>>(Wqkv, z1ss, u1ss, nullptr, DM_, 0);

    dim3 g1(QL_ / 128, DM_ / 128, 1);
    gemm_tc<<<g1, 256, GEMM_SMEM>>>(Wr, pos, nullptr, nullptr, DM_, 1);

    dim3 ga(QL_ / 64, NH_, BSZ_);
    attn_kernel<<<ga, 256, ATTN_SMEM>>>(rwb, rrb);

    dim3 g2(QL_ / 128, DM_ / 128, BSZ_);
    gemm_tc<<<g2, 256, GEMM_SMEM>>>(Wo, nullptr, z1ss, bo, DM_, 2);

    dim3 g3(QL_ / 32, BSZ_);
    ln_kernel<<<g3, 256>>>(out);
}

// round 4
// speedup vs baseline: 2.0090x; 1.4749x over previous
#include <cuda_runtime.h>
#include <cstdint>

#define BSZ_   2
#define DM_    1024
#define QL_    2048
#define NH_    16
#define DH_    64
#define LOCAL_ 1000
#define SCALE_ 0.125f
#define RPAD_  2176   // QL_ + 128 zero-padded row stride for g_R

// ---------------- scratch (__device__ globals; zero-initialized) ---------------
__device__ __align__(16) float g_Q[BSZ_*DM_*QL_];    // [b][n*64+d][pos]
__device__ __align__(16) float g_K[BSZ_*DM_*QL_];
__device__ __align__(16) float g_V[BSZ_*DM_*QL_];
__device__ __align__(16) float g_R[DM_*RPAD_];       // [n*64+d][pos], padded cols stay 0
__device__ __align__(16) float g_AV[BSZ_*DM_*QL_];
__device__ __align__(16) float g_TMP[BSZ_*DM_*QL_];

__device__ __forceinline__ uint32_t f2tf32(float f) {
    uint32_t o; asm("cvt.rna.tf32.f32 %0, %1;" : "=r"(o) : "f"(f)); return o;
}

#define MMA_TF32(C, Af, Bf)                                                     \
    asm volatile(                                                               \
        "mma.sync.aligned.m16n8k8.row.col.f32.tf32.tf32.f32 "                   \
        "{%0,%1,%2,%3}, {%4,%5,%6,%7}, {%8,%9}, {%0,%1,%2,%3};"                 \
        : "+f"((C)[0]), "+f"((C)[1]), "+f"((C)[2]), "+f"((C)[3])                \
        : "r"((Af)[0]), "r"((Af)[1]), "r"((Af)[2]), "r"((Af)[3]),               \
          "r"((Bf)[0]), "r"((Bf)[1]))

// =====================================================================
// tf32 GEMM: C[128x128]/CTA, warp 64x32, K-tile 32, single-buffer, 2 CTA/SM
// =====================================================================
#define GK_STRIDE 136
#define GK_BUF    (32 * GK_STRIDE)
#define GEMM_SMEM (2 * GK_BUF * 4)

__global__ void __launch_bounds__(256, 2) gemm_tc(
    const float* __restrict__ A, const float* __restrict__ Bbase,
    const float* __restrict__ U, const float* __restrict__ bias,
    int K, int mode)
{
    extern __shared__ uint32_t smem_u[];
    uint32_t* As = smem_u;              // [32][136] k-major
    uint32_t* Bs = smem_u + GK_BUF;     // [32][136]

    const int N = QL_;
    const int b = blockIdx.z;
    const float* B = (mode == 2) ? g_AV + (size_t)b * K * N
                   : (mode == 0) ? Bbase + (size_t)b * K * N
                   : Bbase;

    const int m0 = blockIdx.y * 128, n0 = blockIdx.x * 128;
    const int tid  = threadIdx.x;
    const int wid  = tid >> 5, lane = tid & 31;
    const int g    = lane >> 2, q = lane & 3;
    const int wm   = wid >> 2, wn = wid & 3;

    const int am = tid >> 1, akq = (tid & 1) * 16;
    const int bk = tid >> 3, bn = (tid & 7) * 16;

    const float* Ag = A + (size_t)(m0 + am) * K + akq;
    const float* Bg = B + (size_t)bk * N + n0 + bn;

    float acc[4][4][4];
    #pragma unroll
    for (int i = 0; i < 4; i++)
        #pragma unroll
        for (int j = 0; j < 4; j++)
            #pragma unroll
            for (int c = 0; c < 4; c++) acc[i][j][c] = 0.0f;

    for (int k0 = 0; k0 < K; k0 += 32) {
        float4 ra[4], rb[4];
        #pragma unroll
        for (int i = 0; i < 4; i++) ra[i] = *(const float4*)(Ag + k0 + 4 * i);
        #pragma unroll
        for (int i = 0; i < 4; i++) rb[i] = *(const float4*)(Bg + (size_t)k0 * N + 4 * i);

        __syncthreads();   // previous MMA phase done reading smem
        #pragma unroll
        for (int i = 0; i < 4; i++) {
            float v[4] = {ra[i].x, ra[i].y, ra[i].z, ra[i].w};
            #pragma unroll
            for (int c = 0; c < 4; c++)
                As[(akq + 4 * i + c) * GK_STRIDE + am] = f2tf32(v[c]);
        }
        #pragma unroll
        for (int i = 0; i < 4; i++) {
            uint4 o = {f2tf32(rb[i].x), f2tf32(rb[i].y), f2tf32(rb[i].z), f2tf32(rb[i].w)};
            *(uint4*)&Bs[bk * GK_STRIDE + bn + 4 * i] = o;
        }
        __syncthreads();   // tile ready

        #pragma unroll
        for (int kk = 0; kk < 4; kk++) {
            const int kb = kk * 8;
            uint32_t af[4][4], bf[4][2];
            #pragma unroll
            for (int tm = 0; tm < 4; tm++) {
                const int m = wm * 64 + tm * 16 + g;
                af[tm][0] = As[(kb + q) * GK_STRIDE + m];
                af[tm][1] = As[(kb + q) * GK_STRIDE + m + 8];
                af[tm][2] = As[(kb + q + 4) * GK_STRIDE + m];
                af[tm][3] = As[(kb + q + 4) * GK_STRIDE + m + 8];
            }
            #pragma unroll
            for (int tn = 0; tn < 4; tn++) {
                const int n = wn * 32 + tn * 8 + g;
                bf[tn][0] = Bs[(kb + q) * GK_STRIDE + n];
                bf[tn][1] = Bs[(kb + q + 4) * GK_STRIDE + n];
            }
            #pragma unroll
            for (int tm = 0; tm < 4; tm++)
                #pragma unroll
                for (int tn = 0; tn < 4; tn++)
                    MMA_TF32(acc[tm][tn], af[tm], bf[tn]);
        }
    }

    #pragma unroll
    for (int tm = 0; tm < 4; tm++) {
        #pragma unroll
        for (int half = 0; half < 2; half++) {
            const int m = m0 + wm * 64 + tm * 16 + g + half * 8;
            #pragma unroll
            for (int tn = 0; tn < 4; tn++) {
                const int n = n0 + wn * 32 + tn * 8 + 2 * q;
                float v0 = acc[tm][tn][half * 2 + 0];
                float v1 = acc[tm][tn][half * 2 + 1];
                if (mode == 0) {
                    const float2 u = *(const float2*)&U[((size_t)b * 3 * DM_ + m) * QL_ + n];
                    v0 += u.x; v1 += u.y;
                    const int which = m >> 10, rem = m & 1023;
                    float* dst = (which == 0) ? g_Q : (which == 1) ? g_K : g_V;
                    *(float2*)&dst[((size_t)b * DM_ + rem) * QL_ + n] = make_float2(v0, v1);
                } else if (mode == 1) {
                    *(float2*)&g_R[(size_t)m * RPAD_ + n] = make_float2(v0, v1);
                } else {
                    const float bb = bias[m];
                    const float2 u = *(const float2*)&U[((size_t)b * DM_ + m) * QL_ + n];
                    v0 += bb + u.x; v1 += bb + u.y;
                    *(float2*)&g_TMP[((size_t)b * DM_ + m) * QL_ + n] = make_float2(v0, v1);
                }
            }
        }
    }
}

// =====================================================================
// tensor-core banded flash attention with rel-shift
//   per CTA: 64 queries x one head x one batch; 8 warps (2x4)
//   AC = Qw^T K (64x64), E = Qr^T R (64x128), gather BD[i][j]=E[i][j-i+63]
// =====================================================================
#define AQ_S 68    // i-major stride (Qw,Qr,sS/P/sO)
#define AK_S 72    // k/d-major stride (K, Vt)
#define AR_S 136   // R d-major, 128 cols
#define AE_S 132   // E i-major, 128 cols

#define OFF_QW 0
#define OFF_QR (OFF_QW + 64*AQ_S)     // 4352
#define OFF_K  (OFF_QR + 64*AQ_S)     // 8704
#define OFF_VT (OFF_K  + 64*AK_S)     // 13312
#define OFF_R  (OFF_VT + 64*AK_S)     // 17920
#define OFF_S  (OFF_R  + 64*AR_S)     // 26624  (S -> P -> O staging)
#define OFF_E  (OFF_S  + 64*AQ_S)     // 30976
#define OFF_M  (OFF_E  + 64*AE_S)     // 39424
#define OFF_L  (OFF_M + 64)
#define OFF_C  (OFF_L + 64)
#define ATTN_SMEM ((OFF_C + 64) * 4)

__global__ void __launch_bounds__(256) attn_tc(
    const float* __restrict__ rwb_all, const float* __restrict__ rrb_all)
{
    extern __shared__ float sm[];
    uint32_t* smu = (uint32_t*)sm;

    const int b = blockIdx.z, n = blockIdx.y;
    const int i0 = blockIdx.x * 64;
    const int tid = threadIdx.x;
    const int lane = tid & 31, wid = tid >> 5;
    const int g = lane >> 2, q = lane & 3;
    const int wm = wid >> 2, wn = wid & 3;

    const float* Qg = g_Q + ((size_t)b * DM_ + n * DH_) * QL_;
    const float* Kg = g_K + ((size_t)b * DM_ + n * DH_) * QL_;
    const float* Vg = g_V + ((size_t)b * DM_ + n * DH_) * QL_;
    const float* Rg = g_R + (size_t)(n * DH_) * RPAD_;

    if (tid < 64) {
        sm[OFF_M + tid] = -1e30f;
        sm[OFF_L + tid] = 0.0f;
        sm[OFF_C + tid] = 0.0f;
    }
    // Qw/Qr: transpose [d][i] -> [i][d], add biases, cvt to tf32
    for (int idx = tid; idx < 64 * 16; idx += 256) {
        int d = idx >> 4, ic = (idx & 15) * 4;
        float4 v = *(const float4*)&Qg[(size_t)d * QL_ + i0 + ic];
        float w = rwb_all[n * DH_ + d];
        float r = rrb_all[n * DH_ + d];
        float vv[4] = {v.x, v.y, v.z, v.w};
        #pragma unroll
        for (int c = 0; c < 4; c++) {
            smu[OFF_QW + (ic + c) * AQ_S + d] = f2tf32(vv[c] + w);
            smu[OFF_QR + (ic + c) * AQ_S + d] = f2tf32(vv[c] + r);
        }
    }

    float accO[2][2][4];
    #pragma unroll
    for (int a = 0; a < 2; a++)
        #pragma unroll
        for (int c = 0; c < 2; c++)
            #pragma unroll
            for (int e = 0; e < 4; e++) accO[a][c][e] = 0.0f;

    int jlo = i0 - (LOCAL_ - 1); if (jlo < 0) jlo = 0; jlo &= ~63;

    for (int j0 = jlo; j0 <= i0; j0 += 64) {
        __syncthreads();
        // ---- load K [d][j], Vt [j][d], R [d][L] ----
        for (int idx = tid; idx < 64 * 16; idx += 256) {
            int d = idx >> 4, jc = (idx & 15) * 4;
            float4 v = *(const float4*)&Kg[(size_t)d * QL_ + j0 + jc];
            uint4 o = {f2tf32(v.x), f2tf32(v.y), f2tf32(v.z), f2tf32(v.w)};
            *(uint4*)&smu[OFF_K + d * AK_S + jc] = o;
        }
        for (int idx = tid; idx < 64 * 16; idx += 256) {
            int d = idx >> 4, jc = (idx & 15) * 4;
            float4 v = *(const float4*)&Vg[(size_t)d * QL_ + j0 + jc];
            smu[OFF_VT + (jc + 0) * AK_S + d] = f2tf32(v.x);
            smu[OFF_VT + (jc + 1) * AK_S + d] = f2tf32(v.y);
            smu[OFF_VT + (jc + 2) * AK_S + d] = f2tf32(v.z);
            smu[OFF_VT + (jc + 3) * AK_S + d] = f2tf32(v.w);
        }
        const int rbase = j0 - i0 + (QL_ - 1) - 63;   // >= 922, +127 < RPAD_
        for (int idx = tid; idx < 64 * 32; idx += 256) {
            int d = idx >> 5, lc = (idx & 31) * 4;
            float4 v = *(const float4*)&Rg[(size_t)d * RPAD_ + rbase + lc];
            uint4 o = {f2tf32(v.x), f2tf32(v.y), f2tf32(v.z), f2tf32(v.w)};
            *(uint4*)&smu[OFF_R + d * AR_S + lc] = o;
        }
        __syncthreads();

        // ---- S phase: AC (64x64) + E (64x128) ----
        {
            float accS[2][2][4] = {};
            float accE[2][4][4] = {};
            #pragma unroll
            for (int kb = 0; kb < 64; kb += 8) {
                uint32_t aw[2][4], ar[2][4];
                #pragma unroll
                for (int tm = 0; tm < 2; tm++) {
                    int row = wm * 32 + tm * 16 + g;
                    aw[tm][0] = smu[OFF_QW + row * AQ_S + kb + q];
                    aw[tm][1] = smu[OFF_QW + (row + 8) * AQ_S + kb + q];
                    aw[tm][2] = smu[OFF_QW + row * AQ_S + kb + q + 4];
                    aw[tm][3] = smu[OFF_QW + (row + 8) * AQ_S + kb + q + 4];
                    ar[tm][0] = smu[OFF_QR + row * AQ_S + kb + q];
                    ar[tm][1] = smu[OFF_QR + (row + 8) * AQ_S + kb + q];
                    ar[tm][2] = smu[OFF_QR + row * AQ_S + kb + q + 4];
                    ar[tm][3] = smu[OFF_QR + (row + 8) * AQ_S + kb + q + 4];
                }
                #pragma unroll
                for (int tn = 0; tn < 2; tn++) {
                    int col = wn * 16 + tn * 8 + g;
                    uint32_t bf[2];
                    bf[0] = smu[OFF_K + (kb + q) * AK_S + col];
                    bf[1] = smu[OFF_K + (kb + q + 4) * AK_S + col];
                    MMA_TF32(accS[0][tn], aw[0], bf);
                    MMA_TF32(accS[1][tn], aw[1], bf);
                }
                #pragma unroll
                for (int tn = 0; tn < 4; tn++) {
                    int col = wn * 32 + tn * 8 + g;
                    uint32_t bf[2];
                    bf[0] = smu[OFF_R + (kb + q) * AR_S + col];
                    bf[1] = smu[OFF_R + (kb + q + 4) * AR_S + col];
                    MMA_TF32(accE[0][tn], ar[0], bf);
                    MMA_TF32(accE[1][tn], ar[1], bf);
                }
            }
            #pragma unroll
            for (int tm = 0; tm < 2; tm++) {
                int row = wm * 32 + tm * 16 + g;
                #pragma unroll
                for (int tn = 0; tn < 2; tn++) {
                    int col = wn * 16 + tn * 8 + 2 * q;
                    *(float2*)&sm[OFF_S + row * AQ_S + col]       = make_float2(accS[tm][tn][0], accS[tm][tn][1]);
                    *(float2*)&sm[OFF_S + (row + 8) * AQ_S + col] = make_float2(accS[tm][tn][2], accS[tm][tn][3]);
                }
                #pragma unroll
                for (int tn = 0; tn < 4; tn++) {
                    int col = wn * 32 + tn * 8 + 2 * q;
                    *(float2*)&sm[OFF_E + row * AE_S + col]       = make_float2(accE[tm][tn][0], accE[tm][tn][1]);
                    *(float2*)&sm[OFF_E + (row + 8) * AE_S + col] = make_float2(accE[tm][tn][2], accE[tm][tn][3]);
                }
            }
        }
        __syncthreads();

        // ---- softmax (SIMT, 4x4 micro per thread) ----
        {
            const int tx = tid & 15, ty = tid >> 4;
            float s[4][4];
            #pragma unroll
            for (int m = 0; m < 4; m++) {
                int i = ty * 4 + m, gi = i0 + i;
                float4 sv = *(const float4*)&sm[OFF_S + i * AQ_S + tx * 4];
                float svr[4] = {sv.x, sv.y, sv.z, sv.w};
                #pragma unroll
                for (int t = 0; t < 4; t++) {
                    int j = tx * 4 + t, gj = j0 + j;
                    float v = svr[t] + sm[OFF_E + i * AE_S + (j - i + 63)];
                    bool ok = (gj <= gi) && (gj > gi - LOCAL_);
                    s[m][t] = ok ? v * SCALE_ : -1e30f;
                }
            }
            float rmax[4], rsum[4], mo[4], mn[4];
            #pragma unroll
            for (int m = 0; m < 4; m++)
                rmax[m] = fmaxf(fmaxf(s[m][0], s[m][1]), fmaxf(s[m][2], s[m][3]));
            #pragma unroll
            for (int o = 8; o >= 1; o >>= 1)
                #pragma unroll
                for (int m = 0; m < 4; m++)
                    rmax[m] = fmaxf(rmax[m], __shfl_xor_sync(0xffffffffu, rmax[m], o));
            #pragma unroll
            for (int m = 0; m < 4; m++) {
                mo[m] = sm[OFF_M + ty * 4 + m];
                mn[m] = fmaxf(mo[m], rmax[m]);
                rsum[m] = 0.0f;
                #pragma unroll
                for (int t = 0; t < 4; t++) {
                    float p = __expf(s[m][t] - mn[m]);
                    s[m][t] = p;
                    rsum[m] += p;
                }
            }
            #pragma unroll
            for (int o = 8; o >= 1; o >>= 1)
                #pragma unroll
                for (int m = 0; m < 4; m++)
                    rsum[m] += __shfl_xor_sync(0xffffffffu, rsum[m], o);
            __syncwarp();
            if (tx == 0) {
                #pragma unroll
                for (int m = 0; m < 4; m++) {
                    int i = ty * 4 + m;
                    float cc = __expf(mo[m] - mn[m]);
                    sm[OFF_C + i] = cc;
                    sm[OFF_L + i] = sm[OFF_L + i] * cc + rsum[m];
                    sm[OFF_M + i] = mn[m];
                }
            }
            // P (tf32) back into the S buffer
            #pragma unroll
            for (int m = 0; m < 4; m++) {
                int i = ty * 4 + m;
                #pragma unroll
                for (int t = 0; t < 4; t++)
                    smu[OFF_S + i * AQ_S + tx * 4 + t] = f2tf32(s[m][t]);
            }
        }
        __syncthreads();

        // ---- PV: O[i][d] = cc*O + P.V  ----
        {
            #pragma unroll
            for (int tm = 0; tm < 2; tm++) {
                int row = wm * 32 + tm * 16 + g;
                float fa = sm[OFF_C + row], fb = sm[OFF_C + row + 8];
                #pragma unroll
                for (int tn = 0; tn < 2; tn++) {
                    accO[tm][tn][0] *= fa; accO[tm][tn][1] *= fa;
                    accO[tm][tn][2] *= fb; accO[tm][tn][3] *= fb;
                }
            }
            #pragma unroll
            for (int kb = 0; kb < 64; kb += 8) {
                uint32_t ap[2][4];
                #pragma unroll
                for (int tm = 0; tm < 2; tm++) {
                    int row = wm * 32 + tm * 16 + g;
                    ap[tm][0] = smu[OFF_S + row * AQ_S + kb + q];
                    ap[tm][1] = smu[OFF_S + (row + 8) * AQ_S + kb + q];
                    ap[tm][2] = smu[OFF_S + row * AQ_S + kb + q + 4];
                    ap[tm][3] = smu[OFF_S + (row + 8) * AQ_S + kb + q + 4];
                }
                #pragma unroll
                for (int tn = 0; tn < 2; tn++) {
                    int col = wn * 16 + tn * 8 + g;
                    uint32_t bf[2];
                    bf[0] = smu[OFF_VT + (kb + q) * AK_S + col];
                    bf[1] = smu[OFF_VT + (kb + q + 4) * AK_S + col];
                    MMA_TF32(accO[0][tn], ap[0], bf);
                    MMA_TF32(accO[1][tn], ap[1], bf);
                }
            }
        }
    }

    // ---- epilogue: divide by L, transpose through smem, coalesced store ----
    __syncthreads();
    #pragma unroll
    for (int tm = 0; tm < 2; tm++) {
        int row = wm * 32 + tm * 16 + g;
        float la = 1.0f / sm[OFF_L + row];
        float lb = 1.0f / sm[OFF_L + row + 8];
        #pragma unroll
        for (int tn = 0; tn < 2; tn++) {
            int col = wn * 16 + tn * 8 + 2 * q;
            sm[OFF_S + (col + 0) * AQ_S + row]     = accO[tm][tn][0] * la;
            sm[OFF_S + (col + 1) * AQ_S + row]     = accO[tm][tn][1] * la;
            sm[OFF_S + (col + 0) * AQ_S + row + 8] = accO[tm][tn][2] * lb;
            sm[OFF_S + (col + 1) * AQ_S + row + 8] = accO[tm][tn][3] * lb;
        }
    }
    __syncthreads();
    float* AVg = g_AV + ((size_t)b * DM_ + n * DH_) * QL_;
    for (int idx = tid; idx < 64 * 16; idx += 256) {
        int d = idx >> 4, ic = (idx & 15) * 4;
        *(float4*)&AVg[(size_t)d * QL_ + i0 + ic] = *(const float4*)&sm[OFF_S + d * AQ_S + ic];
    }
}

// ---------------- post-LN over d_model per (b, q) ------------------------------
__global__ void __launch_bounds__(256) ln_kernel(float* __restrict__ out)
{
    const int b  = blockIdx.y;
    const int tx = threadIdx.x & 31;
    const int ty = threadIdx.x >> 5;
    const int q  = blockIdx.x * 32 + tx;
    const float* X = g_TMP + (size_t)b * DM_ * QL_;

    float s = 0.0f, s2 = 0.0f;
    for (int o = ty; o < DM_; o += 8) {
        float v = X[(size_t)o * QL_ + q];
        s += v; s2 += v * v;
    }
    __shared__ float sh[8][32], sh2[8][32];
    __shared__ float mu[32], rs[32];
    sh[ty][tx] = s; sh2[ty][tx] = s2;
    __syncthreads();
    if (ty == 0) {
        float ts = 0.0f, ts2 = 0.0f;
        #pragma unroll
        for (int k = 0; k < 8; k++) { ts += sh[k][tx]; ts2 += sh2[k][tx]; }
        float m = ts * (1.0f / DM_);
        float var = ts2 * (1.0f / DM_) - m * m;
        mu[tx] = m;
        rs[tx] = rsqrtf(var + 1e-5f);
    }
    __syncthreads();
    float m = mu[tx], r = rs[tx];
    float* O = out + (size_t)b * DM_ * QL_;
    for (int o = ty; o < DM_; o += 8)
        O[(size_t)o * QL_ + q] = (X[(size_t)o * QL_ + q] - m) * r;
}

// ---------------- launch --------------------------------------------------------
extern "C" void kernel_launch(void* const* d_in, const int* in_sizes, int n_in,
                              void* d_out, int out_size)
{
    const float* z1ss = (const float*)d_in[0];
    const float* pos  = (const float*)d_in[1];
    const float* u1ss = (const float*)d_in[2];
    const float* Wqkv = (const float*)d_in[3];
    const float* Wr   = (const float*)d_in[4];
    const float* rwb  = (const float*)d_in[5];
    const float* rrb  = (const float*)d_in[6];
    const float* Wo   = (const float*)d_in[7];
    const float* bo   = (const float*)d_in[8];
    float* out = (float*)d_out;

    cudaFuncSetAttribute(gemm_tc, cudaFuncAttributeMaxDynamicSharedMemorySize, GEMM_SMEM);
    cudaFuncSetAttribute(attn_tc, cudaFuncAttributeMaxDynamicSharedMemorySize, (int)ATTN_SMEM);

    dim3 g0(QL_ / 128, (3 * DM_) / 128, BSZ_);
    gemm_tc<<<g0, 256, GEMM_SMEM>>>(Wqkv, z1ss, u1ss, nullptr, DM_, 0);

    dim3 g1(QL_ / 128, DM_ / 128, 1);
    gemm_tc<<<g1, 256, GEMM_SMEM>>>(Wr, pos, nullptr, nullptr, DM_, 1);

    dim3 ga(QL_ / 64, NH_, BSZ_);
    attn_tc<<<ga, 256, ATTN_SMEM>>>(rwb, rrb);

    dim3 g2(QL_ / 128, DM_ / 128, BSZ_);
    gemm_tc<<<g2, 256, GEMM_SMEM>>>(Wo, nullptr, z1ss, bo, DM_, 2);

    dim3 g3(QL_ / 32, BSZ_);
    ln_kernel<<<g3, 256>>>(out);
}

// round 5
// speedup vs baseline: 3.7471x; 1.8652x over previous
#include <cuda_runtime.h>
#include <cuda_fp16.h>
#include <cstdint>

#define BSZ_   2
#define DM_    1024
#define QL_    2048
#define NH_    16
#define DH_    64
#define LOCAL_ 1000
#define SCALE_ 0.125f
#define RPAD_  2176   // QL_ + 128 zero-padded row stride for g_R

// ---------------- scratch (__device__ globals; zero-initialized) ---------------
__device__ __align__(16) float g_Q[BSZ_*DM_*QL_];
__device__ __align__(16) float g_K[BSZ_*DM_*QL_];
__device__ __align__(16) float g_V[BSZ_*DM_*QL_];
__device__ __align__(16) float g_R[DM_*RPAD_];
__device__ __align__(16) float g_AV[BSZ_*DM_*QL_];
__device__ __align__(16) float g_TMP[BSZ_*DM_*QL_];

__device__ __forceinline__ uint32_t f22u(float a, float b) {
    __half2 h = __floats2half2_rn(a, b);
    return *reinterpret_cast<uint32_t*>(&h);
}

#define MMA_F16(C, A, B)                                                        \
    asm volatile(                                                               \
        "mma.sync.aligned.m16n8k16.row.col.f32.f16.f16.f32 "                    \
        "{%0,%1,%2,%3}, {%4,%5,%6,%7}, {%8,%9}, {%0,%1,%2,%3};"                 \
        : "+f"((C)[0]), "+f"((C)[1]), "+f"((C)[2]), "+f"((C)[3])                \
        : "r"((A)[0]), "r"((A)[1]), "r"((A)[2]), "r"((A)[3]),                   \
          "r"((B)[0]), "r"((B)[1]))

#define LDSM4(R, addr)                                                          \
    asm volatile("ldmatrix.sync.aligned.m8n8.x4.shared.b16 {%0,%1,%2,%3}, [%4];"\
        : "=r"((R)[0]), "=r"((R)[1]), "=r"((R)[2]), "=r"((R)[3]) : "r"(addr))

#define LDSM4T(R, addr)                                                         \
    asm volatile("ldmatrix.sync.aligned.m8n8.x4.trans.shared.b16 {%0,%1,%2,%3}, [%4];"\
        : "=r"((R)[0]), "=r"((R)[1]), "=r"((R)[2]), "=r"((R)[3]) : "r"(addr))

// =====================================================================
// fp16 GEMM: C[128x128]/CTA, warp 64x32, K-tile 32, ldmatrix fragments
// =====================================================================
#define GA_ST 40    // A tile row stride (halves), 128 x 32 halves
#define GB_ST 136   // B tile row stride (halves), 32 x 128 halves
#define GEMM_A_BYTES (128 * GA_ST * 2)
#define GEMM_SMEM    (GEMM_A_BYTES + 32 * GB_ST * 2)

__global__ void __launch_bounds__(256, 2) gemm_tc(
    const float* __restrict__ A, const float* __restrict__ Bbase,
    const float* __restrict__ U, const float* __restrict__ bias,
    int K, int mode)
{
    extern __shared__ char smc[];
    uint32_t* Aw = (uint32_t*)smc;                    // half2 view of A tile
    uint32_t* Bw = (uint32_t*)(smc + GEMM_A_BYTES);
    const uint32_t sA = (uint32_t)__cvta_generic_to_shared(smc);
    const uint32_t sB = sA + GEMM_A_BYTES;

    const int N = QL_;
    const int b = blockIdx.z;
    const float* B = (mode == 2) ? g_AV + (size_t)b * K * N
                   : (mode == 0) ? Bbase + (size_t)b * K * N
                   : Bbase;

    const int m0 = blockIdx.y * 128, n0 = blockIdx.x * 128;
    const int tid  = threadIdx.x;
    const int wid  = tid >> 5, lane = tid & 31;
    const int g    = lane >> 2, q = lane & 3;
    const int wm   = wid >> 2, wn = wid & 3;

    const int am = tid >> 1, akq = (tid & 1) * 16;
    const int bk = tid >> 3, bn = (tid & 7) * 16;

    const float* Ag = A + (size_t)(m0 + am) * K + akq;
    const float* Bg = B + (size_t)bk * N + n0 + bn;

    // precomputed fragment addresses (bytes)
    uint32_t a_addr[4], b_addr[2];
    #pragma unroll
    for (int tm = 0; tm < 4; tm++)
        a_addr[tm] = sA + ((wm * 64 + tm * 16 + (lane & 15)) * GA_ST + (lane >> 4) * 8) * 2;
    #pragma unroll
    for (int p = 0; p < 2; p++)
        b_addr[p] = sB + ((lane & 15) * GB_ST + wn * 32 + p * 16 + (lane >> 4) * 8) * 2;

    float acc[4][4][4];
    #pragma unroll
    for (int i = 0; i < 4; i++)
        #pragma unroll
        for (int j = 0; j < 4; j++)
            #pragma unroll
            for (int c = 0; c < 4; c++) acc[i][j][c] = 0.0f;

    for (int k0 = 0; k0 < K; k0 += 32) {
        float4 ra[4], rb[4];
        #pragma unroll
        for (int i = 0; i < 4; i++) ra[i] = *(const float4*)(Ag + k0 + 4 * i);
        #pragma unroll
        for (int i = 0; i < 4; i++) rb[i] = *(const float4*)(Bg + (size_t)k0 * N + 4 * i);

        __syncthreads();
        #pragma unroll
        for (int i = 0; i < 4; i++) {
            Aw[am * (GA_ST/2) + (tid & 1) * 8 + 2 * i]     = f22u(ra[i].x, ra[i].y);
            Aw[am * (GA_ST/2) + (tid & 1) * 8 + 2 * i + 1] = f22u(ra[i].z, ra[i].w);
        }
        #pragma unroll
        for (int i = 0; i < 4; i++) {
            Bw[bk * (GB_ST/2) + (tid & 7) * 8 + 2 * i]     = f22u(rb[i].x, rb[i].y);
            Bw[bk * (GB_ST/2) + (tid & 7) * 8 + 2 * i + 1] = f22u(rb[i].z, rb[i].w);
        }
        __syncthreads();

        #pragma unroll
        for (int kk = 0; kk < 2; kk++) {
            const int kbB = kk * 16 * 2;   // byte offset along k for A rows / B rows
            uint32_t af[4][4], bt[2][4];
            #pragma unroll
            for (int tm = 0; tm < 4; tm++) LDSM4(af[tm], a_addr[tm] + kbB);
            #pragma unroll
            for (int p = 0; p < 2; p++)   LDSM4T(bt[p], b_addr[p] + kbB * GB_ST / 1 * 0 + (kk * 16) * GB_ST * 2);
            #pragma unroll
            for (int tm = 0; tm < 4; tm++)
                #pragma unroll
                for (int tn = 0; tn < 4; tn++)
                    MMA_F16(acc[tm][tn], af[tm], &bt[tn >> 1][(tn & 1) * 2]);
        }
    }

    #pragma unroll
    for (int tm = 0; tm < 4; tm++) {
        #pragma unroll
        for (int half = 0; half < 2; half++) {
            const int m = m0 + wm * 64 + tm * 16 + g + half * 8;
            #pragma unroll
            for (int tn = 0; tn < 4; tn++) {
                const int n = n0 + wn * 32 + tn * 8 + 2 * q;
                float v0 = acc[tm][tn][half * 2 + 0];
                float v1 = acc[tm][tn][half * 2 + 1];
                if (mode == 0) {
                    const float2 u = *(const float2*)&U[((size_t)b * 3 * DM_ + m) * QL_ + n];
                    v0 += u.x; v1 += u.y;
                    const int which = m >> 10, rem = m & 1023;
                    float* dst = (which == 0) ? g_Q : (which == 1) ? g_K : g_V;
                    *(float2*)&dst[((size_t)b * DM_ + rem) * QL_ + n] = make_float2(v0, v1);
                } else if (mode == 1) {
                    *(float2*)&g_R[(size_t)m * RPAD_ + n] = make_float2(v0, v1);
                } else {
                    const float bb = bias[m];
                    const float2 u = *(const float2*)&U[((size_t)b * DM_ + m) * QL_ + n];
                    v0 += bb + u.x; v1 += bb + u.y;
                    *(float2*)&g_TMP[((size_t)b * DM_ + m) * QL_ + n] = make_float2(v0, v1);
                }
            }
        }
    }
}

// =====================================================================
// fp16 tensor-core banded flash attention with rel-shift
// =====================================================================
#define AQ_ST 72    // halves: hQW/hQR/hK/hV/hP row stride
#define AR_ST 136   // halves: hR row stride
#define FS_ST 68    // fp32 words
#define FE_ST 132

#define H_QW 0
#define H_QR (H_QW + 64*AQ_ST*2)      // 9216
#define H_K  (H_QR + 64*AQ_ST*2)
#define H_V  (H_K  + 64*AQ_ST*2)
#define H_P  (H_V  + 64*AQ_ST*2)
#define H_R  (H_P  + 64*AQ_ST*2)
#define F_S  (H_R  + 64*AR_ST*2)
#define F_E  (F_S  + 64*FS_ST*4)
#define F_M  (F_E  + 64*FE_ST*4)
#define F_L  (F_M + 256)
#define F_C  (F_L + 256)
#define ATTN_SMEM (F_C + 256)

__global__ void __launch_bounds__(256) attn_tc(
    const float* __restrict__ rwb_all, const float* __restrict__ rrb_all)
{
    extern __shared__ char smc[];
    const uint32_t sb = (uint32_t)__cvta_generic_to_shared(smc);
    __half* hQW = (__half*)(smc + H_QW);
    __half* hQR = (__half*)(smc + H_QR);
    uint32_t* hKw = (uint32_t*)(smc + H_K);
    uint32_t* hVw = (uint32_t*)(smc + H_V);
    uint32_t* hPw = (uint32_t*)(smc + H_P);
    uint32_t* hRw = (uint32_t*)(smc + H_R);
    float* fS = (float*)(smc + F_S);
    float* fE = (float*)(smc + F_E);
    float* fM = (float*)(smc + F_M);
    float* fL = (float*)(smc + F_L);
    float* fC = (float*)(smc + F_C);

    const int b = blockIdx.z, n = blockIdx.y;
    const int i0 = blockIdx.x * 64;
    const int tid = threadIdx.x;
    const int lane = tid & 31, wid = tid >> 5;
    const int g = lane >> 2, q = lane & 3;
    const int wm = wid >> 2, wn = wid & 3;

    const float* Qg = g_Q + ((size_t)b * DM_ + n * DH_) * QL_;
    const float* Kg = g_K + ((size_t)b * DM_ + n * DH_) * QL_;
    const float* Vg = g_V + ((size_t)b * DM_ + n * DH_) * QL_;
    const float* Rg = g_R + (size_t)(n * DH_) * RPAD_;

    if (tid < 64) {
        fM[tid] = -1e30f;
        fL[tid] = 0.0f;
        fC[tid] = 0.0f;
    }
    // Q staging: [d][i] fp32 -> [i][d] half with biases
    for (int idx = tid; idx < 64 * 16; idx += 256) {
        int d = idx >> 4, ic = (idx & 15) * 4;
        float4 v = *(const float4*)&Qg[(size_t)d * QL_ + i0 + ic];
        float w = rwb_all[n * DH_ + d];
        float r = rrb_all[n * DH_ + d];
        float vv[4] = {v.x, v.y, v.z, v.w};
        #pragma unroll
        for (int c = 0; c < 4; c++) {
            hQW[(ic + c) * AQ_ST + d] = __float2half_rn(vv[c] + w);
            hQR[(ic + c) * AQ_ST + d] = __float2half_rn(vv[c] + r);
        }
    }

    // fragment byte addresses
    uint32_t qw_addr[2], qr_addr[2], p_addr[2], k_addr, r_addr[2], v_addr;
    #pragma unroll
    for (int tm = 0; tm < 2; tm++) {
        uint32_t ro = (wm * 32 + tm * 16 + (lane & 15)) * AQ_ST + (lane >> 4) * 8;
        qw_addr[tm] = sb + H_QW + ro * 2;
        qr_addr[tm] = sb + H_QR + ro * 2;
        p_addr[tm]  = sb + H_P  + ro * 2;
    }
    k_addr = sb + H_K + ((lane & 15) * AQ_ST + wn * 16 + (lane >> 4) * 8) * 2;
    #pragma unroll
    for (int p = 0; p < 2; p++)
        r_addr[p] = sb + H_R + ((lane & 15) * AR_ST + wn * 32 + p * 16 + (lane >> 4) * 8) * 2;
    v_addr = sb + H_V + ((wn * 16 + (lane & 7) + (lane >> 4) * 8) * AQ_ST + ((lane >> 3) & 1) * 8) * 2;

    float accO[2][2][4];
    #pragma unroll
    for (int a = 0; a < 2; a++)
        #pragma unroll
        for (int c = 0; c < 2; c++)
            #pragma unroll
            for (int e = 0; e < 4; e++) accO[a][c][e] = 0.0f;

    int jlo = i0 - (LOCAL_ - 1); if (jlo < 0) jlo = 0; jlo &= ~63;

    for (int j0 = jlo; j0 <= i0; j0 += 64) {
        __syncthreads();
        // ---- load K[d][j], V[d][j], R[d][L] as halves ----
        for (int idx = tid; idx < 64 * 16; idx += 256) {
            int d = idx >> 4, jc = (idx & 15) * 4;
            float4 kv = *(const float4*)&Kg[(size_t)d * QL_ + j0 + jc];
            hKw[d * (AQ_ST/2) + jc/2]     = f22u(kv.x, kv.y);
            hKw[d * (AQ_ST/2) + jc/2 + 1] = f22u(kv.z, kv.w);
            float4 vv = *(const float4*)&Vg[(size_t)d * QL_ + j0 + jc];
            hVw[d * (AQ_ST/2) + jc/2]     = f22u(vv.x, vv.y);
            hVw[d * (AQ_ST/2) + jc/2 + 1] = f22u(vv.z, vv.w);
        }
        const int rbase = j0 - i0 + (QL_ - 1) - 63;
        for (int idx = tid; idx < 64 * 32; idx += 256) {
            int d = idx >> 5, lc = (idx & 31) * 4;
            float4 rv = *(const float4*)&Rg[(size_t)d * RPAD_ + rbase + lc];
            hRw[d * (AR_ST/2) + lc/2]     = f22u(rv.x, rv.y);
            hRw[d * (AR_ST/2) + lc/2 + 1] = f22u(rv.z, rv.w);
        }
        __syncthreads();

        // ---- S phase: AC (64x64) + E (64x128), k = d = 64 ----
        {
            float accS[2][2][4] = {};
            float accE[2][4][4] = {};
            #pragma unroll
            for (int kk = 0; kk < 4; kk++) {
                const uint32_t koA = kk * 16 * 2;            // byte offset in row (A-side)
                const uint32_t koB = kk * 16 * AQ_ST * 2;    // byte offset across rows (K)
                const uint32_t koR = kk * 16 * AR_ST * 2;    // (R)
                uint32_t aw[2][4], ar[2][4], bk4[4], br[2][4];
                #pragma unroll
                for (int tm = 0; tm < 2; tm++) {
                    LDSM4(aw[tm], qw_addr[tm] + koA);
                    LDSM4(ar[tm], qr_addr[tm] + koA);
                }
                LDSM4T(bk4, k_addr + koB);
                #pragma unroll
                for (int p = 0; p < 2; p++) LDSM4T(br[p], r_addr[p] + koR);
                #pragma unroll
                for (int tm = 0; tm < 2; tm++) {
                    #pragma unroll
                    for (int tn = 0; tn < 2; tn++)
                        MMA_F16(accS[tm][tn], aw[tm], &bk4[tn * 2]);
                    #pragma unroll
                    for (int tn = 0; tn < 4; tn++)
                        MMA_F16(accE[tm][tn], ar[tm], &br[tn >> 1][(tn & 1) * 2]);
                }
            }
            #pragma unroll
            for (int tm = 0; tm < 2; tm++) {
                int row = wm * 32 + tm * 16 + g;
                #pragma unroll
                for (int tn = 0; tn < 2; tn++) {
                    int col = wn * 16 + tn * 8 + 2 * q;
                    *(float2*)&fS[row * FS_ST + col]       = make_float2(accS[tm][tn][0], accS[tm][tn][1]);
                    *(float2*)&fS[(row + 8) * FS_ST + col] = make_float2(accS[tm][tn][2], accS[tm][tn][3]);
                }
                #pragma unroll
                for (int tn = 0; tn < 4; tn++) {
                    int col = wn * 32 + tn * 8 + 2 * q;
                    *(float2*)&fE[row * FE_ST + col]       = make_float2(accE[tm][tn][0], accE[tm][tn][1]);
                    *(float2*)&fE[(row + 8) * FE_ST + col] = make_float2(accE[tm][tn][2], accE[tm][tn][3]);
                }
            }
        }
        __syncthreads();

        // ---- softmax (SIMT) ----
        {
            const int tx = tid & 15, ty = tid >> 4;
            float s[4][4];
            #pragma unroll
            for (int m = 0; m < 4; m++) {
                int i = ty * 4 + m, gi = i0 + i;
                float4 sv = *(const float4*)&fS[i * FS_ST + tx * 4];
                float svr[4] = {sv.x, sv.y, sv.z, sv.w};
                #pragma unroll
                for (int t = 0; t < 4; t++) {
                    int j = tx * 4 + t, gj = j0 + j;
                    float v = svr[t] + fE[i * FE_ST + (j - i + 63)];
                    bool ok = (gj <= gi) && (gj > gi - LOCAL_);
                    s[m][t] = ok ? v * SCALE_ : -1e30f;
                }
            }
            float rmax[4], rsum[4], mo[4], mn[4];
            #pragma unroll
            for (int m = 0; m < 4; m++)
                rmax[m] = fmaxf(fmaxf(s[m][0], s[m][1]), fmaxf(s[m][2], s[m][3]));
            #pragma unroll
            for (int o = 8; o >= 1; o >>= 1)
                #pragma unroll
                for (int m = 0; m < 4; m++)
                    rmax[m] = fmaxf(rmax[m], __shfl_xor_sync(0xffffffffu, rmax[m], o));
            #pragma unroll
            for (int m = 0; m < 4; m++) {
                mo[m] = fM[ty * 4 + m];
                mn[m] = fmaxf(mo[m], rmax[m]);
                rsum[m] = 0.0f;
                #pragma unroll
                for (int t = 0; t < 4; t++) {
                    float p = __expf(s[m][t] - mn[m]);
                    s[m][t] = p;
                    rsum[m] += p;
                }
            }
            #pragma unroll
            for (int o = 8; o >= 1; o >>= 1)
                #pragma unroll
                for (int m = 0; m < 4; m++)
                    rsum[m] += __shfl_xor_sync(0xffffffffu, rsum[m], o);
            __syncwarp();
            if (tx == 0) {
                #pragma unroll
                for (int m = 0; m < 4; m++) {
                    int i = ty * 4 + m;
                    float cc = __expf(mo[m] - mn[m]);
                    fC[i] = cc;
                    fL[i] = fL[i] * cc + rsum[m];
                    fM[i] = mn[m];
                }
            }
            // P -> half
            #pragma unroll
            for (int m = 0; m < 4; m++) {
                int i = ty * 4 + m;
                hPw[i * (AQ_ST/2) + tx * 2]     = f22u(s[m][0], s[m][1]);
                hPw[i * (AQ_ST/2) + tx * 2 + 1] = f22u(s[m][2], s[m][3]);
            }
        }
        __syncthreads();

        // ---- PV: O[i][d] = cc*O + P.V ----
        {
            #pragma unroll
            for (int tm = 0; tm < 2; tm++) {
                int row = wm * 32 + tm * 16 + g;
                float fa = fC[row], fb = fC[row + 8];
                #pragma unroll
                for (int tn = 0; tn < 2; tn++) {
                    accO[tm][tn][0] *= fa; accO[tm][tn][1] *= fa;
                    accO[tm][tn][2] *= fb; accO[tm][tn][3] *= fb;
                }
            }
            #pragma unroll
            for (int kk = 0; kk < 4; kk++) {
                const uint32_t koA = kk * 16 * 2;
                uint32_t ap[2][4], bv[4];
                #pragma unroll
                for (int tm = 0; tm < 2; tm++) LDSM4(ap[tm], p_addr[tm] + koA);
                LDSM4(bv, v_addr + koA);
                #pragma unroll
                for (int tm = 0; tm < 2; tm++)
                    #pragma unroll
                    for (int tn = 0; tn < 2; tn++)
                        MMA_F16(accO[tm][tn], ap[tm], &bv[tn * 2]);
            }
        }
    }

    // ---- epilogue ----
    __syncthreads();
    #pragma unroll
    for (int tm = 0; tm < 2; tm++) {
        int row = wm * 32 + tm * 16 + g;
        float la = 1.0f / fL[row];
        float lb = 1.0f / fL[row + 8];
        #pragma unroll
        for (int tn = 0; tn < 2; tn++) {
            int col = wn * 16 + tn * 8 + 2 * q;
            fS[(col + 0) * FS_ST + row]     = accO[tm][tn][0] * la;
            fS[(col + 1) * FS_ST + row]     = accO[tm][tn][1] * la;
            fS[(col + 0) * FS_ST + row + 8] = accO[tm][tn][2] * lb;
            fS[(col + 1) * FS_ST + row + 8] = accO[tm][tn][3] * lb;
        }
    }
    __syncthreads();
    float* AVg = g_AV + ((size_t)b * DM_ + n * DH_) * QL_;
    for (int idx = tid; idx < 64 * 16; idx += 256) {
        int d = idx >> 4, ic = (idx & 15) * 4;
        *(float4*)&AVg[(size_t)d * QL_ + i0 + ic] = *(const float4*)&fS[d * FS_ST + ic];
    }
}

// ---------------- post-LN over d_model per (b, q) ------------------------------
__global__ void __launch_bounds__(256) ln_kernel(float* __restrict__ out)
{
    const int b  = blockIdx.y;
    const int tx = threadIdx.x & 31;
    const int ty = threadIdx.x >> 5;
    const int q  = blockIdx.x * 32 + tx;
    const float* X = g_TMP + (size_t)b * DM_ * QL_;

    float s = 0.0f, s2 = 0.0f;
    for (int o = ty; o < DM_; o += 8) {
        float v = X[(size_t)o * QL_ + q];
        s += v; s2 += v * v;
    }
    __shared__ float sh[8][32], sh2[8][32];
    __shared__ float mu[32], rs[32];
    sh[ty][tx] = s; sh2[ty][tx] = s2;
    __syncthreads();
    if (ty == 0) {
        float ts = 0.0f, ts2 = 0.0f;
        #pragma unroll
        for (int k = 0; k < 8; k++) { ts += sh[k][tx]; ts2 += sh2[k][tx]; }
        float m = ts * (1.0f / DM_);
        float var = ts2 * (1.0f / DM_) - m * m;
        mu[tx] = m;
        rs[tx] = rsqrtf(var + 1e-5f);
    }
    __syncthreads();
    float m = mu[tx], r = rs[tx];
    float* O = out + (size_t)b * DM_ * QL_;
    for (int o = ty; o < DM_; o += 8)
        O[(size_t)o * QL_ + q] = (X[(size_t)o * QL_ + q] - m) * r;
}

// ---------------- launch --------------------------------------------------------
extern "C" void kernel_launch(void* const* d_in, const int* in_sizes, int n_in,
                              void* d_out, int out_size)
{
    const float* z1ss = (const float*)d_in[0];
    const float* pos  = (const float*)d_in[1];
    const float* u1ss = (const float*)d_in[2];
    const float* Wqkv = (const float*)d_in[3];
    const float* Wr   = (const float*)d_in[4];
    const float* rwb  = (const float*)d_in[5];
    const float* rrb  = (const float*)d_in[6];
    const float* Wo   = (const float*)d_in[7];
    const float* bo   = (const float*)d_in[8];
    float* out = (float*)d_out;

    cudaFuncSetAttribute(gemm_tc, cudaFuncAttributeMaxDynamicSharedMemorySize, GEMM_SMEM);
    cudaFuncSetAttribute(attn_tc, cudaFuncAttributeMaxDynamicSharedMemorySize, (int)ATTN_SMEM);

    dim3 g0(QL_ / 128, (3 * DM_) / 128, BSZ_);
    gemm_tc<<<g0, 256, GEMM_SMEM>>>(Wqkv, z1ss, u1ss, nullptr, DM_, 0);

    dim3 g1(QL_ / 128, DM_ / 128, 1);
    gemm_tc<<<g1, 256, GEMM_SMEM>>>(Wr, pos, nullptr, nullptr, DM_, 1);

    dim3 ga(QL_ / 64, NH_, BSZ_);
    attn_tc<<<ga, 256, ATTN_SMEM>>>(rwb, rrb);

    dim3 g2(QL_ / 128, DM_ / 128, BSZ_);
    gemm_tc<<<g2, 256, GEMM_SMEM>>>(Wo, nullptr, z1ss, bo, DM_, 2);

    dim3 g3(QL_ / 32, BSZ_);
    ln_kernel<<<g3, 256>>>(out);
}

// round 6
// speedup vs baseline: 4.7224x; 1.2603x over previous
#include <cuda_runtime.h>
#include <cuda_fp16.h>
#include <cstdint>

#define BSZ_   2
#define DM_    1024
#define QL_    2048
#define NH_    16
#define DH_    64
#define LOCAL_ 1000
#define SCALE_ 0.125f
#define RPAD_  2176

// ---------------- scratch (__device__ globals; zero-initialized) ---------------
__device__ __align__(16) __half h_Wqkv[3*DM_*DM_];
__device__ __align__(16) __half h_Wr[DM_*DM_];
__device__ __align__(16) __half h_Wo[DM_*DM_];
__device__ __align__(16) __half h_Z[BSZ_*DM_*QL_];
__device__ __align__(16) __half h_Pe[DM_*QL_];
__device__ __align__(16) __half g_Qh[BSZ_*DM_*QL_];
__device__ __align__(16) __half g_Kh[BSZ_*DM_*QL_];
__device__ __align__(16) __half g_Vh[BSZ_*DM_*QL_];
__device__ __align__(16) __half g_Rh[DM_*RPAD_];   // pad cols stay zero
__device__ __align__(16) __half g_AVh[BSZ_*DM_*QL_];
__device__ __align__(16) float  g_TMP[BSZ_*DM_*QL_];

__device__ __forceinline__ uint32_t f22u(float a, float b) {
    __half2 h = __floats2half2_rn(a, b);
    return *reinterpret_cast<uint32_t*>(&h);
}

#define MMA_F16(C, A, B)                                                        \
    asm volatile(                                                               \
        "mma.sync.aligned.m16n8k16.row.col.f32.f16.f16.f32 "                    \
        "{%0,%1,%2,%3}, {%4,%5,%6,%7}, {%8,%9}, {%0,%1,%2,%3};"                 \
        : "+f"((C)[0]), "+f"((C)[1]), "+f"((C)[2]), "+f"((C)[3])                \
        : "r"((A)[0]), "r"((A)[1]), "r"((A)[2]), "r"((A)[3]),                   \
          "r"((B)[0]), "r"((B)[1]))

#define LDSM4(R, addr)                                                          \
    asm volatile("ldmatrix.sync.aligned.m8n8.x4.shared.b16 {%0,%1,%2,%3}, [%4];"\
        : "=r"((R)[0]), "=r"((R)[1]), "=r"((R)[2]), "=r"((R)[3]) : "r"(addr))

#define LDSM4T(R, addr)                                                         \
    asm volatile("ldmatrix.sync.aligned.m8n8.x4.trans.shared.b16 {%0,%1,%2,%3}, [%4];"\
        : "=r"((R)[0]), "=r"((R)[1]), "=r"((R)[2]), "=r"((R)[3]) : "r"(addr))

#define CPA16(dst, src)                                                         \
    asm volatile("cp.async.cg.shared.global [%0], [%1], 16;" :: "r"(dst), "l"(src))
#define CP_COMMIT asm volatile("cp.async.commit_group;")
#define CP_WAIT0  asm volatile("cp.async.wait_group 0;" ::: "memory")

// ---------------- fp32 -> fp16 conversion pass ---------------------------------
__global__ void f2h_kernel(const float* __restrict__ in, int which, int n4)
{
    __half* out = (which == 0) ? h_Wqkv : (which == 1) ? h_Wr :
                  (which == 2) ? h_Wo   : (which == 3) ? h_Z  : h_Pe;
    int i = blockIdx.x * blockDim.x + threadIdx.x;
    if (i < n4) {
        float4 v = ((const float4*)in)[i];
        uint2 o = { f22u(v.x, v.y), f22u(v.z, v.w) };
        ((uint2*)out)[i] = o;
    }
}

// =====================================================================
// fp16 GEMM, cp.async double-buffered. C[128x128]/CTA, warp 64x32, k-tile 32
// mode 0: h_Wqkv @ h_Z (+u1ss fp32) -> g_Qh/g_Kh/g_Vh
// mode 1: h_Wr @ h_Pe              -> g_Rh
// mode 2: h_Wo @ g_AVh (+b_o+z1ss) -> g_TMP (fp32)
// =====================================================================
#define GA_BUF 10240    // 128*40 halves * 2B
#define GB_BUF 8704     // 32*136 halves * 2B
#define GEMM_SMEM (2*GA_BUF + 2*GB_BUF)

__global__ void __launch_bounds__(256, 2) gemm_tc(
    const float* __restrict__ U, const float* __restrict__ bias, int K, int mode)
{
    extern __shared__ char smc[];
    const uint32_t sbase = (uint32_t)__cvta_generic_to_shared(smc);
    const uint32_t sB0 = sbase + 2 * GA_BUF;

    const int N = QL_;
    const int b = blockIdx.z;
    const __half* A = (mode == 0) ? h_Wqkv : (mode == 1) ? h_Wr : h_Wo;
    const __half* B = (mode == 0) ? h_Z + (size_t)b * K * N
                    : (mode == 1) ? h_Pe
                    : g_AVh + (size_t)b * DM_ * QL_;

    const int m0 = blockIdx.y * 128, n0 = blockIdx.x * 128;
    const int tid = threadIdx.x, lane = tid & 31, wid = tid >> 5;
    const int g = lane >> 2, q = lane & 3;
    const int wm = wid >> 2, wn = wid & 3;

    // cp.async mappings
    const int a_row = tid >> 1, a_c = (tid & 1) * 2;   // 2 16B-chunks each
    const int b_row = tid >> 3, b_c = (tid & 7) * 2;
    const __half* AgB = A + (size_t)(m0 + a_row) * K + a_c * 8;
    const __half* BgB = B + (size_t)b_row * N + n0 + b_c * 8;
    const uint32_t daB = sbase + (a_row * 40 + a_c * 8) * 2;
    const uint32_t dbB = sB0 + (b_row * 136 + b_c * 8) * 2;

    // ldmatrix fragment addresses
    uint32_t a_addr[4], b_addr[2];
    #pragma unroll
    for (int tm = 0; tm < 4; tm++)
        a_addr[tm] = sbase + ((wm * 64 + tm * 16 + (lane & 15)) * 40 + (lane >> 4) * 8) * 2;
    #pragma unroll
    for (int p = 0; p < 2; p++)
        b_addr[p] = sB0 + ((lane & 15) * 136 + wn * 32 + p * 16 + (lane >> 4) * 8) * 2;

    float acc[4][4][4];
    #pragma unroll
    for (int i = 0; i < 4; i++)
        #pragma unroll
        for (int j = 0; j < 4; j++)
            #pragma unroll
            for (int c = 0; c < 4; c++) acc[i][j][c] = 0.0f;

    const int nt = K / 32;
    // prefetch tile 0 -> buf 0
    {
        CPA16(daB, AgB); CPA16(daB + 16, AgB + 8);
        CPA16(dbB, BgB); CPA16(dbB + 16, BgB + 8);
        CP_COMMIT;
    }

    for (int t = 0; t < nt; t++) {
        CP_WAIT0;
        __syncthreads();
        if (t + 1 < nt) {
            const int k1 = (t + 1) * 32;
            const uint32_t ao = ((t + 1) & 1) * GA_BUF, bo = ((t + 1) & 1) * GB_BUF;
            CPA16(daB + ao, AgB + k1); CPA16(daB + ao + 16, AgB + k1 + 8);
            const __half* bs = BgB + (size_t)k1 * N;
            CPA16(dbB + bo, bs); CPA16(dbB + bo + 16, bs + 8);
            CP_COMMIT;
        }
        const uint32_t ao = (t & 1) * GA_BUF, bo = (t & 1) * GB_BUF;
        #pragma unroll
        for (int kk = 0; kk < 2; kk++) {
            uint32_t af[4][4], bt[2][4];
            #pragma unroll
            for (int tm = 0; tm < 4; tm++) LDSM4(af[tm], a_addr[tm] + ao + kk * 32);
            #pragma unroll
            for (int p = 0; p < 2; p++)    LDSM4T(bt[p], b_addr[p] + bo + kk * 16 * 136 * 2);
            #pragma unroll
            for (int tm = 0; tm < 4; tm++)
                #pragma unroll
                for (int tn = 0; tn < 4; tn++)
                    MMA_F16(acc[tm][tn], af[tm], &bt[tn >> 1][(tn & 1) * 2]);
        }
    }

    #pragma unroll
    for (int tm = 0; tm < 4; tm++) {
        #pragma unroll
        for (int half = 0; half < 2; half++) {
            const int m = m0 + wm * 64 + tm * 16 + g + half * 8;
            #pragma unroll
            for (int tn = 0; tn < 4; tn++) {
                const int n = n0 + wn * 32 + tn * 8 + 2 * q;
                float v0 = acc[tm][tn][half * 2 + 0];
                float v1 = acc[tm][tn][half * 2 + 1];
                if (mode == 0) {
                    const float2 u = *(const float2*)&U[((size_t)b * 3 * DM_ + m) * QL_ + n];
                    v0 += u.x; v1 += u.y;
                    const int which = m >> 10, rem = m & 1023;
                    __half* dst = (which == 0) ? g_Qh : (which == 1) ? g_Kh : g_Vh;
                    *(uint32_t*)&dst[((size_t)b * DM_ + rem) * QL_ + n] = f22u(v0, v1);
                } else if (mode == 1) {
                    *(uint32_t*)&g_Rh[(size_t)m * RPAD_ + n] = f22u(v0, v1);
                } else {
                    const float bb = bias[m];
                    const float2 u = *(const float2*)&U[((size_t)b * DM_ + m) * QL_ + n];
                    v0 += bb + u.x; v1 += bb + u.y;
                    *(float2*)&g_TMP[((size_t)b * DM_ + m) * QL_ + n] = make_float2(v0, v1);
                }
            }
        }
    }
}

// =====================================================================
// fp16 banded flash attention, cp.async double-buffered K/V/R
// =====================================================================
#define AQ_ST 72
#define AR_ST 136
#define FS_ST 68
#define FE_ST 132

#define H_QW 0
#define H_QR 9216
#define H_P  18432
#define H_K  27648                 // 2 bufs x 9216
#define H_V  46080                 // 2 bufs x 9216
#define H_R  64512                 // 2 bufs x 17408
#define F_S  99328
#define F_E  116736
#define F_M  150528
#define F_L  (F_M + 256)
#define F_C  (F_L + 256)
#define ATTN_SMEM (F_C + 256)

__global__ void __launch_bounds__(256) attn_tc(
    const float* __restrict__ rwb_all, const float* __restrict__ rrb_all)
{
    extern __shared__ char smc[];
    const uint32_t sb = (uint32_t)__cvta_generic_to_shared(smc);
    __half* hQW = (__half*)(smc + H_QW);
    __half* hQR = (__half*)(smc + H_QR);
    uint32_t* hPw = (uint32_t*)(smc + H_P);
    float* fS = (float*)(smc + F_S);
    float* fE = (float*)(smc + F_E);
    float* fM = (float*)(smc + F_M);
    float* fL = (float*)(smc + F_L);
    float* fC = (float*)(smc + F_C);

    const int b = blockIdx.z, n = blockIdx.y;
    const int i0 = blockIdx.x * 64;
    const int tid = threadIdx.x;
    const int lane = tid & 31, wid = tid >> 5;
    const int g = lane >> 2, q = lane & 3;
    const int wm = wid >> 2, wn = wid & 3;

    const __half* Qh = g_Qh + ((size_t)b * DM_ + n * DH_) * QL_;
    const __half* Kh = g_Kh + ((size_t)b * DM_ + n * DH_) * QL_;
    const __half* Vh = g_Vh + ((size_t)b * DM_ + n * DH_) * QL_;
    const __half* Rh = g_Rh + (size_t)(n * DH_) * RPAD_;

    if (tid < 64) {
        fM[tid] = -1e30f;
        fL[tid] = 0.0f;
        fC[tid] = 0.0f;
    }
    // Q staging: [d][i] half -> [i][d] half with biases
    for (int idx = tid; idx < 64 * 16; idx += 256) {
        int d = idx >> 4, ic = (idx & 15) * 4;
        uint2 u = *(const uint2*)&Qh[(size_t)d * QL_ + i0 + ic];
        float2 v01 = __half22float2(*(__half2*)&u.x);
        float2 v23 = __half22float2(*(__half2*)&u.y);
        float w = rwb_all[n * DH_ + d];
        float r = rrb_all[n * DH_ + d];
        float vv[4] = {v01.x, v01.y, v23.x, v23.y};
        #pragma unroll
        for (int c = 0; c < 4; c++) {
            hQW[(ic + c) * AQ_ST + d] = __float2half_rn(vv[c] + w);
            hQR[(ic + c) * AQ_ST + d] = __float2half_rn(vv[c] + r);
        }
    }

    // cp.async source/dst mapping (per thread: 2 K, 2 V, 4 R chunks)
    const int cp_row = tid >> 2;                // 0..63 (d)
    const int cp_kc = (tid & 3) * 2;            // K/V chunk base
    const int cp_rc = (tid & 3) * 4;            // R chunk base
    const uint32_t dK = sb + H_K + (cp_row * 72 + cp_kc * 8) * 2;
    const uint32_t dV = sb + H_V + (cp_row * 72 + cp_kc * 8) * 2;
    const uint32_t dR = sb + H_R + (cp_row * 136 + cp_rc * 8) * 2;
    const __half* sK = Kh + (size_t)cp_row * QL_ + cp_kc * 8;
    const __half* sV = Vh + (size_t)cp_row * QL_ + cp_kc * 8;
    const __half* sR = Rh + (size_t)cp_row * RPAD_ + cp_rc * 8;

    // ldmatrix fragment addresses
    uint32_t qw_addr[2], qr_addr[2], p_addr[2], k_addr, r_addr[2], v_addr;
    #pragma unroll
    for (int tm = 0; tm < 2; tm++) {
        uint32_t ro = (wm * 32 + tm * 16 + (lane & 15)) * AQ_ST + (lane >> 4) * 8;
        qw_addr[tm] = sb + H_QW + ro * 2;
        qr_addr[tm] = sb + H_QR + ro * 2;
        p_addr[tm]  = sb + H_P  + ro * 2;
    }
    k_addr = sb + H_K + ((lane & 15) * AQ_ST + wn * 16 + (lane >> 4) * 8) * 2;
    #pragma unroll
    for (int p = 0; p < 2; p++)
        r_addr[p] = sb + H_R + ((lane & 15) * AR_ST + wn * 32 + p * 16 + (lane >> 4) * 8) * 2;
    v_addr = sb + H_V + ((wn * 16 + (lane & 7) + (lane >> 4) * 8) * AQ_ST + ((lane >> 3) & 1) * 8) * 2;

    float accO[2][2][4];
    #pragma unroll
    for (int a = 0; a < 2; a++)
        #pragma unroll
        for (int c = 0; c < 2; c++)
            #pragma unroll
            for (int e = 0; e < 4; e++) accO[a][c][e] = 0.0f;

    int jlo = i0 - (LOCAL_ - 1); if (jlo < 0) jlo = 0; jlo &= ~63;
    const int ntile = (i0 - jlo) / 64 + 1;

    // prefetch tile 0 -> buf 0
    {
        const int rbase = jlo - i0 + (QL_ - 1) - 63;
        CPA16(dK, sK + jlo); CPA16(dK + 16, sK + jlo + 8);
        CPA16(dV, sV + jlo); CPA16(dV + 16, sV + jlo + 8);
        const __half* r0 = sR + rbase;
        CPA16(dR, r0); CPA16(dR + 16, r0 + 8); CPA16(dR + 32, r0 + 16); CPA16(dR + 48, r0 + 24);
        CP_COMMIT;
    }

    for (int t = 0; t < ntile; t++) {
        const int j0 = jlo + t * 64;
        CP_WAIT0;
        __syncthreads();
        if (t + 1 < ntile) {
            const int j1 = j0 + 64;
            const int rb1 = j1 - i0 + (QL_ - 1) - 63;
            const uint32_t kb = ((t + 1) & 1) * 9216, rbuf = ((t + 1) & 1) * 17408;
            CPA16(dK + kb, sK + j1); CPA16(dK + kb + 16, sK + j1 + 8);
            CPA16(dV + kb, sV + j1); CPA16(dV + kb + 16, sV + j1 + 8);
            const __half* r1 = sR + rb1;
            CPA16(dR + rbuf, r1); CPA16(dR + rbuf + 16, r1 + 8);
            CPA16(dR + rbuf + 32, r1 + 16); CPA16(dR + rbuf + 48, r1 + 24);
            CP_COMMIT;
        }
        const uint32_t kb = (t & 1) * 9216, rbuf = (t & 1) * 17408;

        // ---- S phase: AC (64x64) + E (64x128) ----
        {
            float accS[2][2][4] = {};
            float accE[2][4][4] = {};
            #pragma unroll
            for (int kk = 0; kk < 4; kk++) {
                const uint32_t koA = kk * 16 * 2;
                const uint32_t koB = kk * 16 * AQ_ST * 2;
                const uint32_t koR = kk * 16 * AR_ST * 2;
                uint32_t aw[2][4], ar[2][4], bk4[4], br[2][4];
                #pragma unroll
                for (int tm = 0; tm < 2; tm++) {
                    LDSM4(aw[tm], qw_addr[tm] + koA);
                    LDSM4(ar[tm], qr_addr[tm] + koA);
                }
                LDSM4T(bk4, k_addr + kb + koB);
                #pragma unroll
                for (int p = 0; p < 2; p++) LDSM4T(br[p], r_addr[p] + rbuf + koR);
                #pragma unroll
                for (int tm = 0; tm < 2; tm++) {
                    #pragma unroll
                    for (int tn = 0; tn < 2; tn++)
                        MMA_F16(accS[tm][tn], aw[tm], &bk4[tn * 2]);
                    #pragma unroll
                    for (int tn = 0; tn < 4; tn++)
                        MMA_F16(accE[tm][tn], ar[tm], &br[tn >> 1][(tn & 1) * 2]);
                }
            }
            #pragma unroll
            for (int tm = 0; tm < 2; tm++) {
                int row = wm * 32 + tm * 16 + g;
                #pragma unroll
                for (int tn = 0; tn < 2; tn++) {
                    int col = wn * 16 + tn * 8 + 2 * q;
                    *(float2*)&fS[row * FS_ST + col]       = make_float2(accS[tm][tn][0], accS[tm][tn][1]);
                    *(float2*)&fS[(row + 8) * FS_ST + col] = make_float2(accS[tm][tn][2], accS[tm][tn][3]);
                }
                #pragma unroll
                for (int tn = 0; tn < 4; tn++) {
                    int col = wn * 32 + tn * 8 + 2 * q;
                    *(float2*)&fE[row * FE_ST + col]       = make_float2(accE[tm][tn][0], accE[tm][tn][1]);
                    *(float2*)&fE[(row + 8) * FE_ST + col] = make_float2(accE[tm][tn][2], accE[tm][tn][3]);
                }
            }
        }
        __syncthreads();

        // ---- softmax ----
        {
            const int tx = tid & 15, ty = tid >> 4;
            float s[4][4];
            #pragma unroll
            for (int m = 0; m < 4; m++) {
                int i = ty * 4 + m, gi = i0 + i;
                float4 sv = *(const float4*)&fS[i * FS_ST + tx * 4];
                float svr[4] = {sv.x, sv.y, sv.z, sv.w};
                #pragma unroll
                for (int t2 = 0; t2 < 4; t2++) {
                    int j = tx * 4 + t2, gj = j0 + j;
                    float v = svr[t2] + fE[i * FE_ST + (j - i + 63)];
                    bool ok = (gj <= gi) && (gj > gi - LOCAL_);
                    s[m][t2] = ok ? v * SCALE_ : -1e30f;
                }
            }
            float rmax[4], rsum[4], mo[4], mn[4];
            #pragma unroll
            for (int m = 0; m < 4; m++)
                rmax[m] = fmaxf(fmaxf(s[m][0], s[m][1]), fmaxf(s[m][2], s[m][3]));
            #pragma unroll
            for (int o = 8; o >= 1; o >>= 1)
                #pragma unroll
                for (int m = 0; m < 4; m++)
                    rmax[m] = fmaxf(rmax[m], __shfl_xor_sync(0xffffffffu, rmax[m], o));
            #pragma unroll
            for (int m = 0; m < 4; m++) {
                mo[m] = fM[ty * 4 + m];
                mn[m] = fmaxf(mo[m], rmax[m]);
                rsum[m] = 0.0f;
                #pragma unroll
                for (int t2 = 0; t2 < 4; t2++) {
                    float p = __expf(s[m][t2] - mn[m]);
                    s[m][t2] = p;
                    rsum[m] += p;
                }
            }
            #pragma unroll
            for (int o = 8; o >= 1; o >>= 1)
                #pragma unroll
                for (int m = 0; m < 4; m++)
                    rsum[m] += __shfl_xor_sync(0xffffffffu, rsum[m], o);
            __syncwarp();
            if (tx == 0) {
                #pragma unroll
                for (int m = 0; m < 4; m++) {
                    int i = ty * 4 + m;
                    float cc = __expf(mo[m] - mn[m]);
                    fC[i] = cc;
                    fL[i] = fL[i] * cc + rsum[m];
                    fM[i] = mn[m];
                }
            }
            #pragma unroll
            for (int m = 0; m < 4; m++) {
                int i = ty * 4 + m;
                hPw[i * (AQ_ST/2) + tx * 2]     = f22u(s[m][0], s[m][1]);
                hPw[i * (AQ_ST/2) + tx * 2 + 1] = f22u(s[m][2], s[m][3]);
            }
        }
        __syncthreads();

        // ---- PV ----
        {
            #pragma unroll
            for (int tm = 0; tm < 2; tm++) {
                int row = wm * 32 + tm * 16 + g;
                float fa = fC[row], fb = fC[row + 8];
                #pragma unroll
                for (int tn = 0; tn < 2; tn++) {
                    accO[tm][tn][0] *= fa; accO[tm][tn][1] *= fa;
                    accO[tm][tn][2] *= fb; accO[tm][tn][3] *= fb;
                }
            }
            #pragma unroll
            for (int kk = 0; kk < 4; kk++) {
                const uint32_t koA = kk * 16 * 2;
                uint32_t ap[2][4], bv[4];
                #pragma unroll
                for (int tm = 0; tm < 2; tm++) LDSM4(ap[tm], p_addr[tm] + koA);
                LDSM4(bv, v_addr + kb + koA);
                #pragma unroll
                for (int tm = 0; tm < 2; tm++)
                    #pragma unroll
                    for (int tn = 0; tn < 2; tn++)
                        MMA_F16(accO[tm][tn], ap[tm], &bv[tn * 2]);
            }
        }
    }

    // ---- epilogue: /L, transpose through fS, half store ----
    __syncthreads();
    #pragma unroll
    for (int tm = 0; tm < 2; tm++) {
        int row = wm * 32 + tm * 16 + g;
        float la = 1.0f / fL[row];
        float lb = 1.0f / fL[row + 8];
        #pragma unroll
        for (int tn = 0; tn < 2; tn++) {
            int col = wn * 16 + tn * 8 + 2 * q;
            fS[(col + 0) * FS_ST + row]     = accO[tm][tn][0] * la;
            fS[(col + 1) * FS_ST + row]     = accO[tm][tn][1] * la;
            fS[(col + 0) * FS_ST + row + 8] = accO[tm][tn][2] * lb;
            fS[(col + 1) * FS_ST + row + 8] = accO[tm][tn][3] * lb;
        }
    }
    __syncthreads();
    __half* AVh = g_AVh + ((size_t)b * DM_ + n * DH_) * QL_;
    for (int idx = tid; idx < 64 * 8; idx += 256) {
        int d = idx >> 3, ic = (idx & 7) * 8;
        const float* src = &fS[d * FS_ST + ic];
        uint4 o;
        o.x = f22u(src[0], src[1]); o.y = f22u(src[2], src[3]);
        o.z = f22u(src[4], src[5]); o.w = f22u(src[6], src[7]);
        *(uint4*)&AVh[(size_t)d * QL_ + i0 + ic] = o;
    }
}

// ---------------- post-LN over d_model per (b, q) ------------------------------
__global__ void __launch_bounds__(256) ln_kernel(float* __restrict__ out)
{
    const int b  = blockIdx.y;
    const int tx = threadIdx.x & 31;
    const int ty = threadIdx.x >> 5;
    const int q  = blockIdx.x * 32 + tx;
    const float* X = g_TMP + (size_t)b * DM_ * QL_;

    float s = 0.0f, s2 = 0.0f;
    for (int o = ty; o < DM_; o += 8) {
        float v = X[(size_t)o * QL_ + q];
        s += v; s2 += v * v;
    }
    __shared__ float sh[8][32], sh2[8][32];
    __shared__ float mu[32], rs[32];
    sh[ty][tx] = s; sh2[ty][tx] = s2;
    __syncthreads();
    if (ty == 0) {
        float ts = 0.0f, ts2 = 0.0f;
        #pragma unroll
        for (int k = 0; k < 8; k++) { ts += sh[k][tx]; ts2 += sh2[k][tx]; }
        float m = ts * (1.0f / DM_);
        float var = ts2 * (1.0f / DM_) - m * m;
        mu[tx] = m;
        rs[tx] = rsqrtf(var + 1e-5f);
    }
    __syncthreads();
    float m = mu[tx], r = rs[tx];
    float* O = out + (size_t)b * DM_ * QL_;
    for (int o = ty; o < DM_; o += 8)
        O[(size_t)o * QL_ + q] = (X[(size_t)o * QL_ + q] - m) * r;
}

// ---------------- launch --------------------------------------------------------
extern "C" void kernel_launch(void* const* d_in, const int* in_sizes, int n_in,
                              void* d_out, int out_size)
{
    const float* z1ss = (const float*)d_in[0];
    const float* pos  = (const float*)d_in[1];
    const float* u1ss = (const float*)d_in[2];
    const float* Wqkv = (const float*)d_in[3];
    const float* Wr   = (const float*)d_in[4];
    const float* rwb  = (const float*)d_in[5];
    const float* rrb  = (const float*)d_in[6];
    const float* Wo   = (const float*)d_in[7];
    const float* bo   = (const float*)d_in[8];
    float* out = (float*)d_out;

    cudaFuncSetAttribute(gemm_tc, cudaFuncAttributeMaxDynamicSharedMemorySize, GEMM_SMEM);
    cudaFuncSetAttribute(attn_tc, cudaFuncAttributeMaxDynamicSharedMemorySize, (int)ATTN_SMEM);

    // fp32 -> fp16 conversions
    auto conv = [&](const float* p, int which, int nelem) {
        int n4 = nelem / 4;
        f2h_kernel<<<(n4 + 255) / 256, 256>>>(p, which, n4);
    };
    conv(Wqkv, 0, 3 * DM_ * DM_);
    conv(Wr,   1, DM_ * DM_);
    conv(Wo,   2, DM_ * DM_);
    conv(z1ss, 3, BSZ_ * DM_ * QL_);
    conv(pos,  4, DM_ * QL_);

    dim3 g0(QL_ / 128, (3 * DM_) / 128, BSZ_);
    gemm_tc<<<g0, 256, GEMM_SMEM>>>(u1ss, nullptr, DM_, 0);

    dim3 g1(QL_ / 128, DM_ / 128, 1);
    gemm_tc<<<g1, 256, GEMM_SMEM>>>(nullptr, nullptr, DM_, 1);

    dim3 ga(QL_ / 64, NH_, BSZ_);
    attn_tc<<<ga, 256, ATTN_SMEM>>>(rwb, rrb);

    dim3 g2(QL_ / 128, DM_ / 128, BSZ_);
    gemm_tc<<<g2, 256, GEMM_SMEM>>>(z1ss, bo, DM_, 2);

    dim3 g3(QL_ / 32, BSZ_);
    ln_kernel<<<g3, 256>>>(out);
}

// round 8
// speedup vs baseline: 5.1072x; 1.0815x over previous
#include <cuda_runtime.h>
#include <cuda_fp16.h>
#include <cstdint>

#define BSZ_   2
#define DM_    1024
#define QL_    2048
#define NH_    16
#define DH_    64
#define LOCAL_ 1000
#define SCALE_ 0.125f
#define RPAD_  2176
#define CML_   (0.125f * 1.44269504088896f)   // scale * log2(e)

// ---------------- scratch (__device__ globals; zero-initialized) ---------------
__device__ __align__(16) __half h_Wqkv[3*DM_*DM_];
__device__ __align__(16) __half h_Wr[DM_*DM_];
__device__ __align__(16) __half h_Wo[DM_*DM_];
__device__ __align__(16) __half h_Z[BSZ_*DM_*QL_];
__device__ __align__(16) __half h_Pe[DM_*QL_];
__device__ __align__(16) __half g_Qh[BSZ_*DM_*QL_];
__device__ __align__(16) __half g_Kh[BSZ_*DM_*QL_];
__device__ __align__(16) __half g_Vh[BSZ_*DM_*QL_];
__device__ __align__(16) __half g_Rh[DM_*RPAD_];
__device__ __align__(16) __half g_AVh[BSZ_*DM_*QL_];
__device__ __align__(16) float  g_TMP[BSZ_*DM_*QL_];

__device__ __forceinline__ uint32_t f22u(float a, float b) {
    __half2 h = __floats2half2_rn(a, b);
    return *reinterpret_cast<uint32_t*>(&h);
}
__device__ __forceinline__ uint32_t h2ex2(float a, float b) {
    uint32_t h = f22u(a, b), r;
    asm("ex2.approx.f16x2 %0, %1;" : "=r"(r) : "r"(h));
    return r;
}

#define MMA_F16(C, A, B)                                                        \
    asm volatile(                                                               \
        "mma.sync.aligned.m16n8k16.row.col.f32.f16.f16.f32 "                    \
        "{%0,%1,%2,%3}, {%4,%5,%6,%7}, {%8,%9}, {%0,%1,%2,%3};"                 \
        : "+f"((C)[0]), "+f"((C)[1]), "+f"((C)[2]), "+f"((C)[3])                \
        : "r"((A)[0]), "r"((A)[1]), "r"((A)[2]), "r"((A)[3]),                   \
          "r"((B)[0]), "r"((B)[1]))

#define LDSM4(R, addr)                                                          \
    asm volatile("ldmatrix.sync.aligned.m8n8.x4.shared.b16 {%0,%1,%2,%3}, [%4];"\
        : "=r"((R)[0]), "=r"((R)[1]), "=r"((R)[2]), "=r"((R)[3]) : "r"(addr))

#define LDSM4T(R, addr)                                                         \
    asm volatile("ldmatrix.sync.aligned.m8n8.x4.trans.shared.b16 {%0,%1,%2,%3}, [%4];"\
        : "=r"((R)[0]), "=r"((R)[1]), "=r"((R)[2]), "=r"((R)[3]) : "r"(addr))

#define CPA16(dst, src)                                                         \
    asm volatile("cp.async.cg.shared.global [%0], [%1], 16;" :: "r"(dst), "l"(src))
#define CP_COMMIT asm volatile("cp.async.commit_group;")
#define CP_WAIT0  asm volatile("cp.async.wait_group 0;" ::: "memory")
#define CP_WAIT1  asm volatile("cp.async.wait_group 1;" ::: "memory")

// ---------------- fused fp32 -> fp16 conversion (one launch) -------------------
#define F2H_N4 2883584   // total float4 elements across 5 tensors
__global__ void f2h_all(const float* __restrict__ z, const float* __restrict__ pos,
                        const float* __restrict__ wqkv, const float* __restrict__ wr,
                        const float* __restrict__ wo)
{
    const int nW = 3*DM_*DM_/4, nR = DM_*DM_/4, nZ = BSZ_*DM_*QL_/4, nP = DM_*QL_/4;
    int off = blockIdx.x * blockDim.x + threadIdx.x;
    const float* src; __half* dst;
    if (off < nW)              { src = wqkv; dst = h_Wqkv; }
    else if ((off -= nW) < nR) { src = wr;   dst = h_Wr;  }
    else if ((off -= nR) < nR) { src = wo;   dst = h_Wo;  }
    else if ((off -= nR) < nZ) { src = z;    dst = h_Z;   }
    else if ((off -= nZ) < nP) { src = pos;  dst = h_Pe;  }
    else return;
    float4 v = ((const float4*)src)[off];
    uint2 o = { f22u(v.x, v.y), f22u(v.z, v.w) };
    ((uint2*)dst)[off] = o;
}

// =====================================================================
// fp16 GEMM, 3-stage cp.async pipeline. C[128x128]/CTA, warp 64x32, k-tile 32
// mode 3: fused QKV (+u1ss) and Wr via grid-y decode
// mode 2: h_Wo @ g_AVh (+b_o+z1ss) -> g_TMP (fp32)
// =====================================================================
#define GA_BUF 10240    // 128*40 halves * 2B
#define GB_BUF 8704     // 32*136 halves * 2B
#define GSTG   (GA_BUF + GB_BUF)
#define GEMM_SMEM (3 * GSTG)

__global__ void __launch_bounds__(256, 2) gemm_tc(
    const float* __restrict__ U, const float* __restrict__ bias, int K, int mode)
{
    extern __shared__ char smc[];
    const uint32_t sbase = (uint32_t)__cvta_generic_to_shared(smc);

    int emode, bb, my;
    if (mode == 3) {
        int y = blockIdx.y;
        if (y < 48) { emode = 0; bb = y / 24; my = y % 24; }
        else        { emode = 1; bb = 0;      my = y - 48; }
    } else { emode = 2; bb = blockIdx.z; my = blockIdx.y; }

    const int N = QL_;
    const __half* A = (emode == 0) ? h_Wqkv : (emode == 1) ? h_Wr : h_Wo;
    const __half* B = (emode == 0) ? h_Z + (size_t)bb * K * N
                    : (emode == 1) ? h_Pe
                    : g_AVh + (size_t)bb * DM_ * QL_;

    const int m0 = my * 128, n0 = blockIdx.x * 128;
    const int tid = threadIdx.x, lane = tid & 31, wid = tid >> 5;
    const int g = lane >> 2, q = lane & 3;
    const int wm = wid >> 2, wn = wid & 3;

    const int a_row = tid >> 1, a_c = (tid & 1) * 2;
    const int b_row = tid >> 3, b_c = (tid & 7) * 2;
    const __half* AgB = A + (size_t)(m0 + a_row) * K + a_c * 8;
    const __half* BgB = B + (size_t)b_row * N + n0 + b_c * 8;
    const uint32_t daB = sbase + (a_row * 40 + a_c * 8) * 2;
    const uint32_t dbB = sbase + GA_BUF + (b_row * 136 + b_c * 8) * 2;

    uint32_t a_addr[4], b_addr[2];
    #pragma unroll
    for (int tm = 0; tm < 4; tm++)
        a_addr[tm] = sbase + ((wm * 64 + tm * 16 + (lane & 15)) * 40 + (lane >> 4) * 8) * 2;
    #pragma unroll
    for (int p = 0; p < 2; p++)
        b_addr[p] = sbase + GA_BUF + ((lane & 15) * 136 + wn * 32 + p * 16 + (lane >> 4) * 8) * 2;

    float acc[4][4][4];
    #pragma unroll
    for (int i = 0; i < 4; i++)
        #pragma unroll
        for (int j = 0; j < 4; j++)
            #pragma unroll
            for (int c = 0; c < 4; c++) acc[i][j][c] = 0.0f;

    const int nt = K / 32;
    // prologue: prefetch tiles 0, 1
    #pragma unroll
    for (int t = 0; t < 2; t++) {
        const uint32_t so = t * GSTG;
        const __half* bs = BgB + (size_t)(t * 32) * N;
        CPA16(daB + so, AgB + t * 32); CPA16(daB + so + 16, AgB + t * 32 + 8);
        CPA16(dbB + so, bs);           CPA16(dbB + so + 16, bs + 8);
        CP_COMMIT;
    }

    int buf0 = 0, buf2 = 2;
    for (int t = 0; t < nt; t++) {
        CP_WAIT1;
        __syncthreads();
        if (t + 2 < nt) {
            const int k1 = (t + 2) * 32;
            const uint32_t so = buf2 * GSTG;
            const __half* bs = BgB + (size_t)k1 * N;
            CPA16(daB + so, AgB + k1); CPA16(daB + so + 16, AgB + k1 + 8);
            CPA16(dbB + so, bs);       CPA16(dbB + so + 16, bs + 8);
        }
        CP_COMMIT;
        const uint32_t so = buf0 * GSTG;
        #pragma unroll
        for (int kk = 0; kk < 2; kk++) {
            uint32_t af[4][4], bt[2][4];
            #pragma unroll
            for (int tm = 0; tm < 4; tm++) LDSM4(af[tm], a_addr[tm] + so + kk * 32);
            #pragma unroll
            for (int p = 0; p < 2; p++)    LDSM4T(bt[p], b_addr[p] + so + kk * 16 * 136 * 2);
            #pragma unroll
            for (int tm = 0; tm < 4; tm++)
                #pragma unroll
                for (int tn = 0; tn < 4; tn++)
                    MMA_F16(acc[tm][tn], af[tm], &bt[tn >> 1][(tn & 1) * 2]);
        }
        buf0 = (buf0 == 2) ? 0 : buf0 + 1;
        buf2 = (buf2 == 2) ? 0 : buf2 + 1;
    }

    #pragma unroll
    for (int tm = 0; tm < 4; tm++) {
        #pragma unroll
        for (int half = 0; half < 2; half++) {
            const int m = m0 + wm * 64 + tm * 16 + g + half * 8;
            #pragma unroll
            for (int tn = 0; tn < 4; tn++) {
                const int n = n0 + wn * 32 + tn * 8 + 2 * q;
                float v0 = acc[tm][tn][half * 2 + 0];
                float v1 = acc[tm][tn][half * 2 + 1];
                if (emode == 0) {
                    const float2 u = *(const float2*)&U[((size_t)bb * 3 * DM_ + m) * QL_ + n];
                    v0 += u.x; v1 += u.y;
                    const int which = m >> 10, rem = m & 1023;
                    __half* dst = (which == 0) ? g_Qh : (which == 1) ? g_Kh : g_Vh;
                    *(uint32_t*)&dst[((size_t)bb * DM_ + rem) * QL_ + n] = f22u(v0, v1);
                } else if (emode == 1) {
                    *(uint32_t*)&g_Rh[(size_t)m * RPAD_ + n] = f22u(v0, v1);
                } else {
                    const float bbia = bias[m];
                    const float2 u = *(const float2*)&U[((size_t)bb * DM_ + m) * QL_ + n];
                    v0 += bbia + u.x; v1 += bbia + u.y;
                    *(float2*)&g_TMP[((size_t)bb * DM_ + m) * QL_ + n] = make_float2(v0, v1);
                }
            }
        }
    }
}

// =====================================================================
// fp16 banded flash attention, cp.async double-buffered K/V/R, f16x2 exp
// =====================================================================
#define AQ_ST 72
#define AR_ST 136
#define FS_ST 68
#define FE_ST 132

#define H_QW 0
#define H_QR 9216
#define H_P  18432
#define H_K  27648
#define H_V  46080
#define H_R  64512
#define F_S  99328
#define F_E  116736
#define F_M  150528
#define F_L  (F_M + 256)
#define F_C  (F_L + 256)
#define ATTN_SMEM (F_C + 256)

__global__ void __launch_bounds__(256) attn_tc(
    const float* __restrict__ rwb_all, const float* __restrict__ rrb_all)
{
    extern __shared__ char smc[];
    const uint32_t sb = (uint32_t)__cvta_generic_to_shared(smc);
    __half* hQW = (__half*)(smc + H_QW);
    __half* hQR = (__half*)(smc + H_QR);
    uint32_t* hPw = (uint32_t*)(smc + H_P);
    float* fS = (float*)(smc + F_S);
    float* fE = (float*)(smc + F_E);
    float* fM = (float*)(smc + F_M);
    float* fL = (float*)(smc + F_L);
    float* fC = (float*)(smc + F_C);

    const int b = blockIdx.z, n = blockIdx.y;
    const int i0 = blockIdx.x * 64;
    const int tid = threadIdx.x;
    const int lane = tid & 31, wid = tid >> 5;
    const int g = lane >> 2, q = lane & 3;
    const int wm = wid >> 2, wn = wid & 3;

    const __half* Qh = g_Qh + ((size_t)b * DM_ + n * DH_) * QL_;
    const __half* Kh = g_Kh + ((size_t)b * DM_ + n * DH_) * QL_;
    const __half* Vh = g_Vh + ((size_t)b * DM_ + n * DH_) * QL_;
    const __half* Rh = g_Rh + (size_t)(n * DH_) * RPAD_;

    if (tid < 64) {
        fM[tid] = -1e30f;
        fL[tid] = 0.0f;
        fC[tid] = 0.0f;
    }
    for (int idx = tid; idx < 64 * 16; idx += 256) {
        int d = idx >> 4, ic = (idx & 15) * 4;
        uint2 u = *(const uint2*)&Qh[(size_t)d * QL_ + i0 + ic];
        float2 v01 = __half22float2(*(__half2*)&u.x);
        float2 v23 = __half22float2(*(__half2*)&u.y);
        float w = rwb_all[n * DH_ + d];
        float r = rrb_all[n * DH_ + d];
        float vv[4] = {v01.x, v01.y, v23.x, v23.y};
        #pragma unroll
        for (int c = 0; c < 4; c++) {
            hQW[(ic + c) * AQ_ST + d] = __float2half_rn(vv[c] + w);
            hQR[(ic + c) * AQ_ST + d] = __float2half_rn(vv[c] + r);
        }
    }

    const int cp_row = tid >> 2;
    const int cp_kc = (tid & 3) * 2;
    const int cp_rc = (tid & 3) * 4;
    const uint32_t dK = sb + H_K + (cp_row * 72 + cp_kc * 8) * 2;
    const uint32_t dV = sb + H_V + (cp_row * 72 + cp_kc * 8) * 2;
    const uint32_t dR = sb + H_R + (cp_row * 136 + cp_rc * 8) * 2;
    const __half* sK = Kh + (size_t)cp_row * QL_ + cp_kc * 8;
    const __half* sV = Vh + (size_t)cp_row * QL_ + cp_kc * 8;
    const __half* sR = Rh + (size_t)cp_row * RPAD_ + cp_rc * 8;

    uint32_t qw_addr[2], qr_addr[2], p_addr[2], k_addr, r_addr[2], v_addr;
    #pragma unroll
    for (int tm = 0; tm < 2; tm++) {
        uint32_t ro = (wm * 32 + tm * 16 + (lane & 15)) * AQ_ST + (lane >> 4) * 8;
        qw_addr[tm] = sb + H_QW + ro * 2;
        qr_addr[tm] = sb + H_QR + ro * 2;
        p_addr[tm]  = sb + H_P  + ro * 2;
    }
    k_addr = sb + H_K + ((lane & 15) * AQ_ST + wn * 16 + (lane >> 4) * 8) * 2;
    #pragma unroll
    for (int p = 0; p < 2; p++)
        r_addr[p] = sb + H_R + ((lane & 15) * AR_ST + wn * 32 + p * 16 + (lane >> 4) * 8) * 2;
    v_addr = sb + H_V + ((wn * 16 + (lane & 7) + (lane >> 4) * 8) * AQ_ST + ((lane >> 3) & 1) * 8) * 2;

    float accO[2][2][4];
    #pragma unroll
    for (int a = 0; a < 2; a++)
        #pragma unroll
        for (int c = 0; c < 2; c++)
            #pragma unroll
            for (int e = 0; e < 4; e++) accO[a][c][e] = 0.0f;

    int jlo = i0 - (LOCAL_ - 1); if (jlo < 0) jlo = 0; jlo &= ~63;
    const int ntile = (i0 - jlo) / 64 + 1;

    {
        const int rbase = jlo - i0 + (QL_ - 1) - 63;
        CPA16(dK, sK + jlo); CPA16(dK + 16, sK + jlo + 8);
        CPA16(dV, sV + jlo); CPA16(dV + 16, sV + jlo + 8);
        const __half* r0 = sR + rbase;
        CPA16(dR, r0); CPA16(dR + 16, r0 + 8); CPA16(dR + 32, r0 + 16); CPA16(dR + 48, r0 + 24);
        CP_COMMIT;
    }

    for (int t = 0; t < ntile; t++) {
        const int j0 = jlo + t * 64;
        CP_WAIT0;
        __syncthreads();
        if (t + 1 < ntile) {
            const int j1 = j0 + 64;
            const int rb1 = j1 - i0 + (QL_ - 1) - 63;
            const uint32_t kb = ((t + 1) & 1) * 9216, rbuf = ((t + 1) & 1) * 17408;
            CPA16(dK + kb, sK + j1); CPA16(dK + kb + 16, sK + j1 + 8);
            CPA16(dV + kb, sV + j1); CPA16(dV + kb + 16, sV + j1 + 8);
            const __half* r1 = sR + rb1;
            CPA16(dR + rbuf, r1); CPA16(dR + rbuf + 16, r1 + 8);
            CPA16(dR + rbuf + 32, r1 + 16); CPA16(dR + rbuf + 48, r1 + 24);
            CP_COMMIT;
        }
        const uint32_t kb = (t & 1) * 9216, rbuf = (t & 1) * 17408;

        // ---- S phase: AC (64x64) + E (64x128) ----
        {
            float accS[2][2][4] = {};
            float accE[2][4][4] = {};
            #pragma unroll
            for (int kk = 0; kk < 4; kk++) {
                const uint32_t koA = kk * 16 * 2;
                const uint32_t koB = kk * 16 * AQ_ST * 2;
                const uint32_t koR = kk * 16 * AR_ST * 2;
                uint32_t aw[2][4], ar[2][4], bk4[4], br[2][4];
                #pragma unroll
                for (int tm = 0; tm < 2; tm++) {
                    LDSM4(aw[tm], qw_addr[tm] + koA);
                    LDSM4(ar[tm], qr_addr[tm] + koA);
                }
                LDSM4T(bk4, k_addr + kb + koB);
                #pragma unroll
                for (int p = 0; p < 2; p++) LDSM4T(br[p], r_addr[p] + rbuf + koR);
                #pragma unroll
                for (int tm = 0; tm < 2; tm++) {
                    #pragma unroll
                    for (int tn = 0; tn < 2; tn++)
                        MMA_F16(accS[tm][tn], aw[tm], &bk4[tn * 2]);
                    #pragma unroll
                    for (int tn = 0; tn < 4; tn++)
                        MMA_F16(accE[tm][tn], ar[tm], &br[tn >> 1][(tn & 1) * 2]);
                }
            }
            #pragma unroll
            for (int tm = 0; tm < 2; tm++) {
                int row = wm * 32 + tm * 16 + g;
                #pragma unroll
                for (int tn = 0; tn < 2; tn++) {
                    int col = wn * 16 + tn * 8 + 2 * q;
                    *(float2*)&fS[row * FS_ST + col]       = make_float2(accS[tm][tn][0], accS[tm][tn][1]);
                    *(float2*)&fS[(row + 8) * FS_ST + col] = make_float2(accS[tm][tn][2], accS[tm][tn][3]);
                }
                #pragma unroll
                for (int tn = 0; tn < 4; tn++) {
                    int col = wn * 32 + tn * 8 + 2 * q;
                    *(float2*)&fE[row * FE_ST + col]       = make_float2(accE[tm][tn][0], accE[tm][tn][1]);
                    *(float2*)&fE[(row + 8) * FE_ST + col] = make_float2(accE[tm][tn][2], accE[tm][tn][3]);
                }
            }
        }
        __syncthreads();

        // ---- softmax (log2 domain, f16x2 exp) ----
        {
            const int tx = tid & 15, ty = tid >> 4;
            const bool needmask = (j0 == i0) || (j0 <= i0 + 63 - LOCAL_);
            float s[4][4];
            #pragma unroll
            for (int m = 0; m < 4; m++) {
                int i = ty * 4 + m, gi = i0 + i;
                float4 sv = *(const float4*)&fS[i * FS_ST + tx * 4];
                float svr[4] = {sv.x, sv.y, sv.z, sv.w};
                #pragma unroll
                for (int t2 = 0; t2 < 4; t2++) {
                    int j = tx * 4 + t2;
                    float v = (svr[t2] + fE[i * FE_ST + (j - i + 63)]) * CML_;
                    if (needmask) {
                        int gj = j0 + j;
                        bool ok = (gj <= gi) && (gj > gi - LOCAL_);
                        v = ok ? v : -1e30f;
                    }
                    s[m][t2] = v;
                }
            }
            float rmax[4], rsum[4], mo[4], mn[4];
            uint32_t pw[4][2];
            #pragma unroll
            for (int m = 0; m < 4; m++)
                rmax[m] = fmaxf(fmaxf(s[m][0], s[m][1]), fmaxf(s[m][2], s[m][3]));
            #pragma unroll
            for (int o = 8; o >= 1; o >>= 1)
                #pragma unroll
                for (int m = 0; m < 4; m++)
                    rmax[m] = fmaxf(rmax[m], __shfl_xor_sync(0xffffffffu, rmax[m], o));
            #pragma unroll
            for (int m = 0; m < 4; m++) {
                mo[m] = fM[ty * 4 + m];
                mn[m] = fmaxf(mo[m], rmax[m]);
                uint32_t p01 = h2ex2(s[m][0] - mn[m], s[m][1] - mn[m]);
                uint32_t p23 = h2ex2(s[m][2] - mn[m], s[m][3] - mn[m]);
                pw[m][0] = p01; pw[m][1] = p23;
                __half2 hs = __hadd2(*(__half2*)&p01, *(__half2*)&p23);
                rsum[m] = __low2float(hs) + __high2float(hs);
            }
            #pragma unroll
            for (int o = 8; o >= 1; o >>= 1)
                #pragma unroll
                for (int m = 0; m < 4; m++)
                    rsum[m] += __shfl_xor_sync(0xffffffffu, rsum[m], o);
            __syncwarp();
            if (tx == 0) {
                #pragma unroll
                for (int m = 0; m < 4; m++) {
                    int i = ty * 4 + m;
                    float cc = exp2f(mo[m] - mn[m]);
                    fC[i] = cc;
                    fL[i] = fL[i] * cc + rsum[m];
                    fM[i] = mn[m];
                }
            }
            #pragma unroll
            for (int m = 0; m < 4; m++) {
                int i = ty * 4 + m;
                hPw[i * (AQ_ST/2) + tx * 2]     = pw[m][0];
                hPw[i * (AQ_ST/2) + tx * 2 + 1] = pw[m][1];
            }
        }
        __syncthreads();

        // ---- PV ----
        {
            #pragma unroll
            for (int tm = 0; tm < 2; tm++) {
                int row = wm * 32 + tm * 16 + g;
                float fa = fC[row], fb = fC[row + 8];
                #pragma unroll
                for (int tn = 0; tn < 2; tn++) {
                    accO[tm][tn][0] *= fa; accO[tm][tn][1] *= fa;
                    accO[tm][tn][2] *= fb; accO[tm][tn][3] *= fb;
                }
            }
            #pragma unroll
            for (int kk = 0; kk < 4; kk++) {
                const uint32_t koA = kk * 16 * 2;
                uint32_t ap[2][4], bv[4];
                #pragma unroll
                for (int tm = 0; tm < 2; tm++) LDSM4(ap[tm], p_addr[tm] + koA);
                LDSM4(bv, v_addr + kb + koA);
                #pragma unroll
                for (int tm = 0; tm < 2; tm++)
                    #pragma unroll
                    for (int tn = 0; tn < 2; tn++)
                        MMA_F16(accO[tm][tn], ap[tm], &bv[tn * 2]);
            }
        }
    }

    // ---- epilogue ----
    __syncthreads();
    #pragma unroll
    for (int tm = 0; tm < 2; tm++) {
        int row = wm * 32 + tm * 16 + g;
        float la = 1.0f / fL[row];
        float lb = 1.0f / fL[row + 8];
        #pragma unroll
        for (int tn = 0; tn < 2; tn++) {
            int col = wn * 16 + tn * 8 + 2 * q;
            fS[(col + 0) * FS_ST + row]     = accO[tm][tn][0] * la;
            fS[(col + 1) * FS_ST + row]     = accO[tm][tn][1] * la;
            fS[(col + 0) * FS_ST + row + 8] = accO[tm][tn][2] * lb;
            fS[(col + 1) * FS_ST + row + 8] = accO[tm][tn][3] * lb;
        }
    }
    __syncthreads();
    __half* AVh = g_AVh + ((size_t)b * DM_ + n * DH_) * QL_;
    for (int idx = tid; idx < 64 * 8; idx += 256) {
        int d = idx >> 3, ic = (idx & 7) * 8;
        const float* src = &fS[d * FS_ST + ic];
        uint4 o;
        o.x = f22u(src[0], src[1]); o.y = f22u(src[2], src[3]);
        o.z = f22u(src[4], src[5]); o.w = f22u(src[6], src[7]);
        *(uint4*)&AVh[(size_t)d * QL_ + i0 + ic] = o;
    }
}

// ---------------- post-LN over d_model per (b, q) ------------------------------
__global__ void __launch_bounds__(256) ln_kernel(float* __restrict__ out)
{
    const int b  = blockIdx.y;
    const int tx = threadIdx.x & 31;
    const int ty = threadIdx.x >> 5;
    const int q  = blockIdx.x * 32 + tx;
    const float* X = g_TMP + (size_t)b * DM_ * QL_;

    float s = 0.0f, s2 = 0.0f;
    for (int o = ty; o < DM_; o += 8) {
        float v = X[(size_t)o * QL_ + q];
        s += v; s2 += v * v;
    }
    __shared__ float sh[8][32], sh2[8][32];
    __shared__ float mu[32], rs[32];
    sh[ty][tx] = s; sh2[ty][tx] = s2;
    __syncthreads();
    if (ty == 0) {
        float ts = 0.0f, ts2 = 0.0f;
        #pragma unroll
        for (int k = 0; k < 8; k++) { ts += sh[k][tx]; ts2 += sh2[k][tx]; }
        float m = ts * (1.0f / DM_);
        float var = ts2 * (1.0f / DM_) - m * m;
        mu[tx] = m;
        rs[tx] = rsqrtf(var + 1e-5f);
    }
    __syncthreads();
    float m = mu[tx], r = rs[tx];
    float* O = out + (size_t)b * DM_ * QL_;
    for (int o = ty; o < DM_; o += 8)
        O[(size_t)o * QL_ + q] = (X[(size_t)o * QL_ + q] - m) * r;
}

// ---------------- launch --------------------------------------------------------
extern "C" void kernel_launch(void* const* d_in, const int* in_sizes, int n_in,
                              void* d_out, int out_size)
{
    const float* z1ss = (const float*)d_in[0];
    const float* pos  = (const float*)d_in[1];
    const float* u1ss = (const float*)d_in[2];
    const float* Wqkv = (const float*)d_in[3];
    const float* Wr   = (const float*)d_in[4];
    const float* rwb  = (const float*)d_in[5];
    const float* rrb  = (const float*)d_in[6];
    const float* Wo   = (const float*)d_in[7];
    const float* bo   = (const float*)d_in[8];
    float* out = (float*)d_out;

    cudaFuncSetAttribute(gemm_tc, cudaFuncAttributeMaxDynamicSharedMemorySize, GEMM_SMEM);
    cudaFuncSetAttribute(attn_tc, cudaFuncAttributeMaxDynamicSharedMemorySize, (int)ATTN_SMEM);

    f2h_all<<<(F2H_N4 + 255) / 256, 256>>>(z1ss, pos, Wqkv, Wr, Wo);

    dim3 g0(QL_ / 128, 56, 1);   // fused QKV (48 y-blocks) + Wr (8 y-blocks)
    gemm_tc<<<g0, 256, GEMM_SMEM>>>(u1ss, nullptr, DM_, 3);

    dim3 ga(QL_ / 64, NH_, BSZ_);
    attn_tc<<<ga, 256, ATTN_SMEM>>>(rwb, rrb);

    dim3 g2(QL_ / 128, DM_ / 128, BSZ_);
    gemm_tc<<<g2, 256, GEMM_SMEM>>>(z1ss, bo, DM_, 2);

    dim3 g3(QL_ / 32, BSZ_);
    ln_kernel<<<g3, 256>>>(out);
}

// round 9
// speedup vs baseline: 5.2791x; 1.0337x over previous
#include <cuda_runtime.h>
#include <cuda_fp16.h>
#include <cstdint>

#define BSZ_   2
#define DM_    1024
#define QL_    2048
#define NH_    16
#define DH_    64
#define LOCAL_ 1000
#define SCALE_ 0.125f
#define RPAD_  2176
#define CML_   (0.125f * 1.44269504088896f)   // scale * log2(e)

// ---------------- scratch (__device__ globals; zero-initialized) ---------------
__device__ __align__(16) __half h_Wqkv[3*DM_*DM_];
__device__ __align__(16) __half h_Wr[DM_*DM_];
__device__ __align__(16) __half h_Wo[DM_*DM_];
__device__ __align__(16) __half h_Z[BSZ_*DM_*QL_];
__device__ __align__(16) __half h_Pe[DM_*QL_];
__device__ __align__(16) __half g_Qh[BSZ_*DM_*QL_];
__device__ __align__(16) __half g_Kh[BSZ_*DM_*QL_];
__device__ __align__(16) __half g_Vh[BSZ_*DM_*QL_];
__device__ __align__(16) __half g_Rh[DM_*RPAD_];
__device__ __align__(16) __half g_AVh[BSZ_*DM_*QL_];
__device__ __align__(16) float  g_TMP[BSZ_*DM_*QL_];

__device__ __forceinline__ uint32_t f22u(float a, float b) {
    __half2 h = __floats2half2_rn(a, b);
    return *reinterpret_cast<uint32_t*>(&h);
}
__device__ __forceinline__ uint32_t h2ex2(float a, float b) {
    uint32_t h = f22u(a, b), r;
    asm("ex2.approx.f16x2 %0, %1;" : "=r"(r) : "r"(h));
    return r;
}

#define MMA_F16(C, A, B)                                                        \
    asm volatile(                                                               \
        "mma.sync.aligned.m16n8k16.row.col.f32.f16.f16.f32 "                    \
        "{%0,%1,%2,%3}, {%4,%5,%6,%7}, {%8,%9}, {%0,%1,%2,%3};"                 \
        : "+f"((C)[0]), "+f"((C)[1]), "+f"((C)[2]), "+f"((C)[3])                \
        : "r"((A)[0]), "r"((A)[1]), "r"((A)[2]), "r"((A)[3]),                   \
          "r"((B)[0]), "r"((B)[1]))

#define LDSM4(R, addr)                                                          \
    asm volatile("ldmatrix.sync.aligned.m8n8.x4.shared.b16 {%0,%1,%2,%3}, [%4];"\
        : "=r"((R)[0]), "=r"((R)[1]), "=r"((R)[2]), "=r"((R)[3]) : "r"(addr))

#define LDSM4T(R, addr)                                                         \
    asm volatile("ldmatrix.sync.aligned.m8n8.x4.trans.shared.b16 {%0,%1,%2,%3}, [%4];"\
        : "=r"((R)[0]), "=r"((R)[1]), "=r"((R)[2]), "=r"((R)[3]) : "r"(addr))

#define CPA16(dst, src)                                                         \
    asm volatile("cp.async.cg.shared.global [%0], [%1], 16;" :: "r"(dst), "l"(src))
#define CP_COMMIT asm volatile("cp.async.commit_group;")
#define CP_WAIT0  asm volatile("cp.async.wait_group 0;" ::: "memory")

// ---------------- fused fp32 -> fp16 conversion (one launch) -------------------
#define F2H_N4 2883584
__global__ void f2h_all(const float* __restrict__ z, const float* __restrict__ pos,
                        const float* __restrict__ wqkv, const float* __restrict__ wr,
                        const float* __restrict__ wo)
{
    const int nW = 3*DM_*DM_/4, nR = DM_*DM_/4, nZ = BSZ_*DM_*QL_/4, nP = DM_*QL_/4;
    int off = blockIdx.x * blockDim.x + threadIdx.x;
    const float* src; __half* dst;
    if (off < nW)              { src = wqkv; dst = h_Wqkv; }
    else if ((off -= nW) < nR) { src = wr;   dst = h_Wr;  }
    else if ((off -= nR) < nR) { src = wo;   dst = h_Wo;  }
    else if ((off -= nR) < nZ) { src = z;    dst = h_Z;   }
    else if ((off -= nZ) < nP) { src = pos;  dst = h_Pe;  }
    else return;
    float4 v = ((const float4*)src)[off];
    uint2 o = { f22u(v.x, v.y), f22u(v.z, v.w) };
    ((uint2*)dst)[off] = o;
}

// =====================================================================
// fp16 GEMM, k-tile 64, 2-stage cp.async. C[128x128]/CTA, warp 64x32
// mode 3: fused QKV (+u1ss) + Wr via grid-y decode;  mode 2: Wo
// =====================================================================
#define GA_BUF 18432    // 128 x 72 halves
#define GB_BUF 17408    // 64 x 136 halves
#define GSTG   (GA_BUF + GB_BUF)
#define GEMM_SMEM (2 * GSTG)

__global__ void __launch_bounds__(256, 2) gemm_tc(
    const float* __restrict__ U, const float* __restrict__ bias, int K, int mode)
{
    extern __shared__ char smc[];
    const uint32_t sbase = (uint32_t)__cvta_generic_to_shared(smc);

    int emode, bb, my;
    if (mode == 3) {
        int y = blockIdx.y;
        if (y < 48) { emode = 0; bb = y / 24; my = y % 24; }
        else        { emode = 1; bb = 0;      my = y - 48; }
    } else { emode = 2; bb = blockIdx.z; my = blockIdx.y; }

    const int N = QL_;
    const __half* A = (emode == 0) ? h_Wqkv : (emode == 1) ? h_Wr : h_Wo;
    const __half* B = (emode == 0) ? h_Z + (size_t)bb * K * N
                    : (emode == 1) ? h_Pe
                    : g_AVh + (size_t)bb * DM_ * QL_;

    const int m0 = my * 128, n0 = blockIdx.x * 128;
    const int tid = threadIdx.x, lane = tid & 31, wid = tid >> 5;
    const int g = lane >> 2, q = lane & 3;
    const int wm = wid >> 2, wn = wid & 3;

    // cp.async mapping: A 128x64, B 64x128 (4x16B per thread each)
    const int a_row = tid >> 1, a_h = (tid & 1) * 32;
    const int b_row = tid >> 2, b_h = (tid & 3) * 32;
    const __half* AgB = A + (size_t)(m0 + a_row) * K + a_h;
    const __half* BgB = B + (size_t)b_row * N + n0 + b_h;
    const uint32_t daB = sbase + (a_row * 72 + a_h) * 2;
    const uint32_t dbB = sbase + GA_BUF + (b_row * 136 + b_h) * 2;

    uint32_t a_addr[4], b_addr[2];
    #pragma unroll
    for (int tm = 0; tm < 4; tm++)
        a_addr[tm] = sbase + ((wm * 64 + tm * 16 + (lane & 15)) * 72 + (lane >> 4) * 8) * 2;
    #pragma unroll
    for (int p = 0; p < 2; p++)
        b_addr[p] = sbase + GA_BUF + ((lane & 15) * 136 + wn * 32 + p * 16 + (lane >> 4) * 8) * 2;

    float acc[4][4][4];
    #pragma unroll
    for (int i = 0; i < 4; i++)
        #pragma unroll
        for (int j = 0; j < 4; j++)
            #pragma unroll
            for (int c = 0; c < 4; c++) acc[i][j][c] = 0.0f;

    const int nt = K / 64;
    {   // prologue: tile 0 -> stage 0
        CPA16(daB, AgB);      CPA16(daB + 16, AgB + 8);
        CPA16(daB + 32, AgB + 16); CPA16(daB + 48, AgB + 24);
        CPA16(dbB, BgB);      CPA16(dbB + 16, BgB + 8);
        CPA16(dbB + 32, BgB + 16); CPA16(dbB + 48, BgB + 24);
        CP_COMMIT;
    }

    for (int t = 0; t < nt; t++) {
        CP_WAIT0;
        __syncthreads();
        if (t + 1 < nt) {
            const int k1 = (t + 1) * 64;
            const uint32_t so = ((t + 1) & 1) * GSTG;
            const __half* as = AgB + k1;
            const __half* bs = BgB + (size_t)k1 * N;
            CPA16(daB + so, as);      CPA16(daB + so + 16, as + 8);
            CPA16(daB + so + 32, as + 16); CPA16(daB + so + 48, as + 24);
            CPA16(dbB + so, bs);      CPA16(dbB + so + 16, bs + 8);
            CPA16(dbB + so + 32, bs + 16); CPA16(dbB + so + 48, bs + 24);
            CP_COMMIT;
        }
        const uint32_t so = (t & 1) * GSTG;
        #pragma unroll
        for (int kk = 0; kk < 4; kk++) {
            uint32_t af[4][4], bt[2][4];
            #pragma unroll
            for (int tm = 0; tm < 4; tm++) LDSM4(af[tm], a_addr[tm] + so + kk * 32);
            #pragma unroll
            for (int p = 0; p < 2; p++)    LDSM4T(bt[p], b_addr[p] + so + kk * 16 * 136 * 2);
            #pragma unroll
            for (int tm = 0; tm < 4; tm++)
                #pragma unroll
                for (int tn = 0; tn < 4; tn++)
                    MMA_F16(acc[tm][tn], af[tm], &bt[tn >> 1][(tn & 1) * 2]);
        }
    }

    #pragma unroll
    for (int tm = 0; tm < 4; tm++) {
        #pragma unroll
        for (int half = 0; half < 2; half++) {
            const int m = m0 + wm * 64 + tm * 16 + g + half * 8;
            #pragma unroll
            for (int tn = 0; tn < 4; tn++) {
                const int n = n0 + wn * 32 + tn * 8 + 2 * q;
                float v0 = acc[tm][tn][half * 2 + 0];
                float v1 = acc[tm][tn][half * 2 + 1];
                if (emode == 0) {
                    const float2 u = *(const float2*)&U[((size_t)bb * 3 * DM_ + m) * QL_ + n];
                    v0 += u.x; v1 += u.y;
                    const int which = m >> 10, rem = m & 1023;
                    __half* dst = (which == 0) ? g_Qh : (which == 1) ? g_Kh : g_Vh;
                    *(uint32_t*)&dst[((size_t)bb * DM_ + rem) * QL_ + n] = f22u(v0, v1);
                } else if (emode == 1) {
                    *(uint32_t*)&g_Rh[(size_t)m * RPAD_ + n] = f22u(v0, v1);
                } else {
                    const float bbia = bias[m];
                    const float2 u = *(const float2*)&U[((size_t)bb * DM_ + m) * QL_ + n];
                    v0 += bbia + u.x; v1 += bbia + u.y;
                    *(float2*)&g_TMP[((size_t)bb * DM_ + m) * QL_ + n] = make_float2(v0, v1);
                }
            }
        }
    }
}

// =====================================================================
// fp16 banded flash attention — 106.8 KB smem, 2 CTA/SM
// S/E stored as half; R single-buffered with mid-tile prefetch
// =====================================================================
#define AQ_ST 72
#define AR_ST 136

#define H_QW 0
#define H_QR 9216
#define H_P  18432
#define H_K  27648          // 2 x 9216
#define H_V  46080          // 2 x 9216
#define H_R  64512          // 1 x 17408
#define H_S  81920          // 64 x 72 halves
#define H_E  91136          // 64 x 136 halves (also fp32 scratch in epilogue)
#define F_M  108544
#define F_L  (F_M + 256)
#define F_C  (F_L + 256)
#define ATTN_SMEM (F_C + 256)

__global__ void __launch_bounds__(256, 2) attn_tc(
    const float* __restrict__ rwb_all, const float* __restrict__ rrb_all)
{
    extern __shared__ char smc[];
    const uint32_t sb = (uint32_t)__cvta_generic_to_shared(smc);
    __half* hQW = (__half*)(smc + H_QW);
    __half* hQR = (__half*)(smc + H_QR);
    uint32_t* hPw = (uint32_t*)(smc + H_P);
    __half* hS = (__half*)(smc + H_S);
    __half* hE = (__half*)(smc + H_E);
    float* fM = (float*)(smc + F_M);
    float* fL = (float*)(smc + F_L);
    float* fC = (float*)(smc + F_C);

    const int b = blockIdx.z, n = blockIdx.y;
    const int i0 = blockIdx.x * 64;
    const int tid = threadIdx.x;
    const int lane = tid & 31, wid = tid >> 5;
    const int g = lane >> 2, q = lane & 3;
    const int wm = wid >> 2, wn = wid & 3;

    const __half* Qh = g_Qh + ((size_t)b * DM_ + n * DH_) * QL_;
    const __half* Kh = g_Kh + ((size_t)b * DM_ + n * DH_) * QL_;
    const __half* Vh = g_Vh + ((size_t)b * DM_ + n * DH_) * QL_;
    const __half* Rh = g_Rh + (size_t)(n * DH_) * RPAD_;

    if (tid < 64) {
        fM[tid] = -1e30f;
        fL[tid] = 0.0f;
        fC[tid] = 0.0f;
    }
    for (int idx = tid; idx < 64 * 16; idx += 256) {
        int d = idx >> 4, ic = (idx & 15) * 4;
        uint2 u = *(const uint2*)&Qh[(size_t)d * QL_ + i0 + ic];
        float2 v01 = __half22float2(*(__half2*)&u.x);
        float2 v23 = __half22float2(*(__half2*)&u.y);
        float w = rwb_all[n * DH_ + d];
        float r = rrb_all[n * DH_ + d];
        float vv[4] = {v01.x, v01.y, v23.x, v23.y};
        #pragma unroll
        for (int c = 0; c < 4; c++) {
            hQW[(ic + c) * AQ_ST + d] = __float2half_rn(vv[c] + w);
            hQR[(ic + c) * AQ_ST + d] = __float2half_rn(vv[c] + r);
        }
    }

    const int cp_row = tid >> 2;
    const int cp_kc = (tid & 3) * 2;
    const int cp_rc = (tid & 3) * 4;
    const uint32_t dK = sb + H_K + (cp_row * 72 + cp_kc * 8) * 2;
    const uint32_t dV = sb + H_V + (cp_row * 72 + cp_kc * 8) * 2;
    const uint32_t dR = sb + H_R + (cp_row * 136 + cp_rc * 8) * 2;
    const __half* sK = Kh + (size_t)cp_row * QL_ + cp_kc * 8;
    const __half* sV = Vh + (size_t)cp_row * QL_ + cp_kc * 8;
    const __half* sR = Rh + (size_t)cp_row * RPAD_ + cp_rc * 8;

    uint32_t qw_addr[2], qr_addr[2], p_addr[2], k_addr, r_addr[2], v_addr;
    #pragma unroll
    for (int tm = 0; tm < 2; tm++) {
        uint32_t ro = (wm * 32 + tm * 16 + (lane & 15)) * AQ_ST + (lane >> 4) * 8;
        qw_addr[tm] = sb + H_QW + ro * 2;
        qr_addr[tm] = sb + H_QR + ro * 2;
        p_addr[tm]  = sb + H_P  + ro * 2;
    }
    k_addr = sb + H_K + ((lane & 15) * AQ_ST + wn * 16 + (lane >> 4) * 8) * 2;
    #pragma unroll
    for (int p = 0; p < 2; p++)
        r_addr[p] = sb + H_R + ((lane & 15) * AR_ST + wn * 32 + p * 16 + (lane >> 4) * 8) * 2;
    v_addr = sb + H_V + ((wn * 16 + (lane & 7) + (lane >> 4) * 8) * AQ_ST + ((lane >> 3) & 1) * 8) * 2;

    float accO[2][2][4];
    #pragma unroll
    for (int a = 0; a < 2; a++)
        #pragma unroll
        for (int c = 0; c < 2; c++)
            #pragma unroll
            for (int e = 0; e < 4; e++) accO[a][c][e] = 0.0f;

    int jlo = i0 - (LOCAL_ - 1); if (jlo < 0) jlo = 0; jlo &= ~63;
    const int ntile = (i0 - jlo) / 64 + 1;

    {   // prologue: K/V/R tile 0
        const int rbase = jlo - i0 + (QL_ - 1) - 63;
        CPA16(dK, sK + jlo); CPA16(dK + 16, sK + jlo + 8);
        CPA16(dV, sV + jlo); CPA16(dV + 16, sV + jlo + 8);
        const __half* r0 = sR + rbase;
        CPA16(dR, r0); CPA16(dR + 16, r0 + 8); CPA16(dR + 32, r0 + 16); CPA16(dR + 48, r0 + 24);
        CP_COMMIT;
    }

    for (int t = 0; t < ntile; t++) {
        const int j0 = jlo + t * 64;
        CP_WAIT0;
        __syncthreads();
        if (t + 1 < ntile) {   // K/V for t+1 (R issued after S phase)
            const int j1 = j0 + 64;
            const uint32_t kb = ((t + 1) & 1) * 9216;
            CPA16(dK + kb, sK + j1); CPA16(dK + kb + 16, sK + j1 + 8);
            CPA16(dV + kb, sV + j1); CPA16(dV + kb + 16, sV + j1 + 8);
            CP_COMMIT;
        }
        const uint32_t kb = (t & 1) * 9216;

        // ---- S phase: AC (64x64) + E (64x128) ----
        {
            float accS[2][2][4] = {};
            float accE[2][4][4] = {};
            #pragma unroll
            for (int kk = 0; kk < 4; kk++) {
                const uint32_t koA = kk * 16 * 2;
                const uint32_t koB = kk * 16 * AQ_ST * 2;
                const uint32_t koR = kk * 16 * AR_ST * 2;
                uint32_t aw[2][4], ar[2][4], bk4[4], br[2][4];
                #pragma unroll
                for (int tm = 0; tm < 2; tm++) {
                    LDSM4(aw[tm], qw_addr[tm] + koA);
                    LDSM4(ar[tm], qr_addr[tm] + koA);
                }
                LDSM4T(bk4, k_addr + kb + koB);
                #pragma unroll
                for (int p = 0; p < 2; p++) LDSM4T(br[p], r_addr[p] + koR);
                #pragma unroll
                for (int tm = 0; tm < 2; tm++) {
                    #pragma unroll
                    for (int tn = 0; tn < 2; tn++)
                        MMA_F16(accS[tm][tn], aw[tm], &bk4[tn * 2]);
                    #pragma unroll
                    for (int tn = 0; tn < 4; tn++)
                        MMA_F16(accE[tm][tn], ar[tm], &br[tn >> 1][(tn & 1) * 2]);
                }
            }
            #pragma unroll
            for (int tm = 0; tm < 2; tm++) {
                int row = wm * 32 + tm * 16 + g;
                #pragma unroll
                for (int tn = 0; tn < 2; tn++) {
                    int col = wn * 16 + tn * 8 + 2 * q;
                    *(uint32_t*)&hS[row * AQ_ST + col]       = f22u(accS[tm][tn][0], accS[tm][tn][1]);
                    *(uint32_t*)&hS[(row + 8) * AQ_ST + col] = f22u(accS[tm][tn][2], accS[tm][tn][3]);
                }
                #pragma unroll
                for (int tn = 0; tn < 4; tn++) {
                    int col = wn * 32 + tn * 8 + 2 * q;
                    *(uint32_t*)&hE[row * AR_ST + col]       = f22u(accE[tm][tn][0], accE[tm][tn][1]);
                    *(uint32_t*)&hE[(row + 8) * AR_ST + col] = f22u(accE[tm][tn][2], accE[tm][tn][3]);
                }
            }
        }
        __syncthreads();

        // R prefetch for t+1 (S phase — R's only reader — is done)
        if (t + 1 < ntile) {
            const int rb1 = (j0 + 64) - i0 + (QL_ - 1) - 63;
            const __half* r1 = sR + rb1;
            CPA16(dR, r1); CPA16(dR + 16, r1 + 8); CPA16(dR + 32, r1 + 16); CPA16(dR + 48, r1 + 24);
            CP_COMMIT;
        }

        // ---- softmax (log2 domain, f16x2 exp) ----
        {
            const int tx = tid & 15, ty = tid >> 4;
            const bool needmask = (j0 == i0) || (j0 <= i0 + 63 - LOCAL_);
            float s[4][4];
            #pragma unroll
            for (int m = 0; m < 4; m++) {
                int i = ty * 4 + m, gi = i0 + i;
                uint2 su = *(const uint2*)&hS[i * AQ_ST + tx * 4];
                float2 s01 = __half22float2(*(__half2*)&su.x);
                float2 s23 = __half22float2(*(__half2*)&su.y);
                float svr[4] = {s01.x, s01.y, s23.x, s23.y};
                const __half* erow = &hE[i * AR_ST + (tx * 4 - i + 63)];
                #pragma unroll
                for (int t2 = 0; t2 < 4; t2++) {
                    float v = (svr[t2] + __half2float(erow[t2])) * CML_;
                    if (needmask) {
                        int gj = j0 + tx * 4 + t2;
                        bool ok = (gj <= gi) && (gj > gi - LOCAL_);
                        v = ok ? v : -1e30f;
                    }
                    s[m][t2] = v;
                }
            }
            float rmax[4], rsum[4], mo[4], mn[4];
            uint32_t pw[4][2];
            #pragma unroll
            for (int m = 0; m < 4; m++)
                rmax[m] = fmaxf(fmaxf(s[m][0], s[m][1]), fmaxf(s[m][2], s[m][3]));
            #pragma unroll
            for (int o = 8; o >= 1; o >>= 1)
                #pragma unroll
                for (int m = 0; m < 4; m++)
                    rmax[m] = fmaxf(rmax[m], __shfl_xor_sync(0xffffffffu, rmax[m], o));
            #pragma unroll
            for (int m = 0; m < 4; m++) {
                mo[m] = fM[ty * 4 + m];
                mn[m] = fmaxf(mo[m], rmax[m]);
                uint32_t p01 = h2ex2(s[m][0] - mn[m], s[m][1] - mn[m]);
                uint32_t p23 = h2ex2(s[m][2] - mn[m], s[m][3] - mn[m]);
                pw[m][0] = p01; pw[m][1] = p23;
                __half2 hs = __hadd2(*(__half2*)&p01, *(__half2*)&p23);
                rsum[m] = __low2float(hs) + __high2float(hs);
            }
            #pragma unroll
            for (int o = 8; o >= 1; o >>= 1)
                #pragma unroll
                for (int m = 0; m < 4; m++)
                    rsum[m] += __shfl_xor_sync(0xffffffffu, rsum[m], o);
            __syncwarp();
            if (tx == 0) {
                #pragma unroll
                for (int m = 0; m < 4; m++) {
                    int i = ty * 4 + m;
                    float cc = exp2f(mo[m] - mn[m]);
                    fC[i] = cc;
                    fL[i] = fL[i] * cc + rsum[m];
                    fM[i] = mn[m];
                }
            }
            #pragma unroll
            for (int m = 0; m < 4; m++) {
                int i = ty * 4 + m;
                hPw[i * (AQ_ST/2) + tx * 2]     = pw[m][0];
                hPw[i * (AQ_ST/2) + tx * 2 + 1] = pw[m][1];
            }
        }
        __syncthreads();

        // ---- PV ----
        {
            #pragma unroll
            for (int tm = 0; tm < 2; tm++) {
                int row = wm * 32 + tm * 16 + g;
                float fa = fC[row], fb = fC[row + 8];
                #pragma unroll
                for (int tn = 0; tn < 2; tn++) {
                    accO[tm][tn][0] *= fa; accO[tm][tn][1] *= fa;
                    accO[tm][tn][2] *= fb; accO[tm][tn][3] *= fb;
                }
            }
            #pragma unroll
            for (int kk = 0; kk < 4; kk++) {
                const uint32_t koA = kk * 16 * 2;
                uint32_t ap[2][4], bv[4];
                #pragma unroll
                for (int tm = 0; tm < 2; tm++) LDSM4(ap[tm], p_addr[tm] + koA);
                LDSM4(bv, v_addr + kb + koA);
                #pragma unroll
                for (int tm = 0; tm < 2; tm++)
                    #pragma unroll
                    for (int tn = 0; tn < 2; tn++)
                        MMA_F16(accO[tm][tn], ap[tm], &bv[tn * 2]);
            }
        }
    }

    // ---- epilogue: /L, transpose via fp32 scratch in hE region, half store ----
    __syncthreads();
    float* fX = (float*)(smc + H_E);   // 64x68 fp32 scratch
    #pragma unroll
    for (int tm = 0; tm < 2; tm++) {
        int row = wm * 32 + tm * 16 + g;
        float la = 1.0f / fL[row];
        float lb = 1.0f / fL[row + 8];
        #pragma unroll
        for (int tn = 0; tn < 2; tn++) {
            int col = wn * 16 + tn * 8 + 2 * q;
            fX[(col + 0) * 68 + row]     = accO[tm][tn][0] * la;
            fX[(col + 1) * 68 + row]     = accO[tm][tn][1] * la;
            fX[(col + 0) * 68 + row + 8] = accO[tm][tn][2] * lb;
            fX[(col + 1) * 68 + row + 8] = accO[tm][tn][3] * lb;
        }
    }
    __syncthreads();
    __half* AVh = g_AVh + ((size_t)b * DM_ + n * DH_) * QL_;
    for (int idx = tid; idx < 64 * 8; idx += 256) {
        int d = idx >> 3, ic = (idx & 7) * 8;
        const float* src = &fX[d * 68 + ic];
        uint4 o;
        o.x = f22u(src[0], src[1]); o.y = f22u(src[2], src[3]);
        o.z = f22u(src[4], src[5]); o.w = f22u(src[6], src[7]);
        *(uint4*)&AVh[(size_t)d * QL_ + i0 + ic] = o;
    }
}

// ---------------- post-LN over d_model per (b, q) ------------------------------
__global__ void __launch_bounds__(256) ln_kernel(float* __restrict__ out)
{
    const int b  = blockIdx.y;
    const int tx = threadIdx.x & 31;
    const int ty = threadIdx.x >> 5;
    const int q  = blockIdx.x * 32 + tx;
    const float* X = g_TMP + (size_t)b * DM_ * QL_;

    float s = 0.0f, s2 = 0.0f;
    for (int o = ty; o < DM_; o += 8) {
        float v = X[(size_t)o * QL_ + q];
        s += v; s2 += v * v;
    }
    __shared__ float sh[8][32], sh2[8][32];
    __shared__ float mu[32], rs[32];
    sh[ty][tx] = s; sh2[ty][tx] = s2;
    __syncthreads();
    if (ty == 0) {
        float ts = 0.0f, ts2 = 0.0f;
        #pragma unroll
        for (int k = 0; k < 8; k++) { ts += sh[k][tx]; ts2 += sh2[k][tx]; }
        float m = ts * (1.0f / DM_);
        float var = ts2 * (1.0f / DM_) - m * m;
        mu[tx] = m;
        rs[tx] = rsqrtf(var + 1e-5f);
    }
    __syncthreads();
    float m = mu[tx], r = rs[tx];
    float* O = out + (size_t)b * DM_ * QL_;
    for (int o = ty; o < DM_; o += 8)
        O[(size_t)o * QL_ + q] = (X[(size_t)o * QL_ + q] - m) * r;
}

// ---------------- launch --------------------------------------------------------
extern "C" void kernel_launch(void* const* d_in, const int* in_sizes, int n_in,
                              void* d_out, int out_size)
{
    const float* z1ss = (const float*)d_in[0];
    const float* pos  = (const float*)d_in[1];
    const float* u1ss = (const float*)d_in[2];
    const float* Wqkv = (const float*)d_in[3];
    const float* Wr   = (const float*)d_in[4];
    const float* rwb  = (const float*)d_in[5];
    const float* rrb  = (const float*)d_in[6];
    const float* Wo   = (const float*)d_in[7];
    const float* bo   = (const float*)d_in[8];
    float* out = (float*)d_out;

    cudaFuncSetAttribute(gemm_tc, cudaFuncAttributeMaxDynamicSharedMemorySize, GEMM_SMEM);
    cudaFuncSetAttribute(attn_tc, cudaFuncAttributeMaxDynamicSharedMemorySize, (int)ATTN_SMEM);

    f2h_all<<<(F2H_N4 + 255) / 256, 256>>>(z1ss, pos, Wqkv, Wr, Wo);

    dim3 g0(QL_ / 128, 56, 1);   // fused QKV (48 y-blocks) + Wr (8 y-blocks)
    gemm_tc<<<g0, 256, GEMM_SMEM>>>(u1ss, nullptr, DM_, 3);

    dim3 ga(QL_ / 64, NH_, BSZ_);
    attn_tc<<<ga, 256, ATTN_SMEM>>>(rwb, rrb);

    dim3 g2(QL_ / 128, DM_ / 128, BSZ_);
    gemm_tc<<<g2, 256, GEMM_SMEM>>>(z1ss, bo, DM_, 2);

    dim3 g3(QL_ / 32, BSZ_);
    ln_kernel<<<g3, 256>>>(out);
}